// round 11
// baseline (speedup 1.0000x reference)
#include <cuda_runtime.h>
#include <cuda_bf16.h>
#include <math.h>
#include <stdint.h>

#define B_  32
#define S_  128
#define T_  64
#define E_  256
#define H_  512
#define V_  32000
#define GH  2048
#define DH  1024
#define DG  4096
#define TD  63
#define MROWS 2016
#define MPAD  2048

// tcgen05 only legal in the compute_103a feature pass.
#if defined(__CUDA_ARCH_FEAT_SM103_ALL) || defined(__CUDA_ARCH_FEAT_SM100_ALL) || !defined(__CUDA_ARCH__)
#define HAS_TC 1
#else
#define HAS_TC 0
#endif

// ---------------- scratch ----------------
__device__ float g_pre_fT[(size_t)S_ * GH * B_];
__device__ float g_pre_bT[(size_t)S_ * GH * B_];
__device__ float g_dec_preT[(size_t)TD * DG * B_];
__device__ float g_enc_hT[2][2][H_ * B_];
__device__ float g_enc_cT[2][H_ * B_];
__device__ float g_dec_hT[2][DH * B_];
__device__ int   g_enc_rowidx[S_ * B_];
__device__ int   g_dec_rowidx[TD * B_];
__device__ __nv_bfloat16 g_Abig[(size_t)MPAD * 2048];   // [hi(1024) | lo(1024)]
__device__ __nv_bfloat16 g_Wbig[(size_t)V_ * 2048];     // [hi | lo]
__device__ unsigned g_sync[192];

// ---------------- grid barrier (R7/R9-proven: fence + acquire) ----------------
__device__ __forceinline__ void grid_barrier2(unsigned* cnt, unsigned* gen,
                                              unsigned step, unsigned nb)
{
    __syncthreads();
    if (threadIdx.x == 0) {
        __threadfence();
        unsigned old;
        asm volatile("atom.add.release.gpu.u32 %0, [%1], 1;"
                     : "=r"(old) : "l"(cnt) : "memory");
        if (old == step * nb - 1) {
            asm volatile("st.release.gpu.u32 [%0], %1;" :: "l"(gen), "r"(step) : "memory");
        } else {
            unsigned v;
            do {
                asm volatile("ld.acquire.gpu.u32 %0, [%1];" : "=r"(v) : "l"(gen) : "memory");
            } while (v < step);
        }
    }
    __syncthreads();
}

// ---------------- f32x2 packed helpers ----------------
__device__ __forceinline__ unsigned long long pk2(float lo, float hi)
{
    unsigned long long p;
    asm("mov.b64 %0, {%1, %2};" : "=l"(p) : "f"(lo), "f"(hi));
    return p;
}
__device__ __forceinline__ unsigned long long ffma2(unsigned long long a,
                                                    unsigned long long b,
                                                    unsigned long long c)
{
    unsigned long long d;
    asm("fma.rn.f32x2 %0, %1, %2, %3;" : "=l"(d) : "l"(a), "l"(b), "l"(c));
    return d;
}
__device__ __forceinline__ void unpk2(unsigned long long p, float& lo, float& hi)
{
    asm("mov.b64 {%0, %1}, %2;" : "=f"(lo), "=f"(hi) : "l"(p));
}

// ---------------- fast activations ----------------
__device__ __forceinline__ float fsig(float x)
{
    float e; asm("ex2.approx.f32 %0, %1;" : "=f"(e) : "f"(-1.4426950408889634f * x));
    float r; asm("rcp.approx.f32 %0, %1;" : "=f"(r) : "f"(1.f + e));
    return r;
}
__device__ __forceinline__ float ftanh(float x)
{
    float e; asm("ex2.approx.f32 %0, %1;" : "=f"(e) : "f"(2.8853900817779268f * x));
    float r; asm("rcp.approx.f32 %0, %1;" : "=f"(r) : "f"(1.f + e));
    return 1.f - 2.f * r;
}

// ---------------- prep ----------------
__global__ void prep_k(const int* __restrict__ src, const int* __restrict__ trg,
                       float* __restrict__ out)
{
    long idx = (long)blockIdx.x * blockDim.x + threadIdx.x;
    const long N0 = (long)B_ * V_;
    if (idx < N0) {
        long b = idx / V_, v = idx - b * V_;
        out[(size_t)b * T_ * V_ + v] = 0.f;
        return;
    }
    idx -= N0;
    if (idx < 2 * H_ * B_) { g_enc_hT[idx >> 14][0][idx & 16383] = 0.f; return; }
    idx -= 2 * H_ * B_;
    if (idx < S_ * B_) {
        int t = (int)(idx / B_), b = (int)(idx % B_);
        g_enc_rowidx[idx] = src[b * S_ + t];
        return;
    }
    idx -= S_ * B_;
    if (idx < TD * B_) {
        int t = (int)(idx / B_), b = (int)(idx % B_);
        g_dec_rowidx[idx] = trg[b * T_ + t];
        return;
    }
    idx -= TD * B_;
    if (idx < 192) { g_sync[idx] = 0; return; }
    idx -= 192;
    if (idx < (MPAD - MROWS) * 2048) {
        g_Abig[(size_t)(MROWS + (idx >> 11)) * 2048 + (idx & 2047)] = __float2bfloat16(0.f);
        return;
    }
}

// ---------------- W split conversion ----------------
__global__ void wconv_k(const float* __restrict__ fcW)
{
    size_t i = (size_t)blockIdx.x * 256 + threadIdx.x;
    if (i >= (size_t)V_ * 256) return;
    size_t n = i >> 8; int k4 = (int)(i & 255);
    float4 v = __ldcg((const float4*)fcW + i);
    __nv_bfloat16 h0 = __float2bfloat16(v.x), h1 = __float2bfloat16(v.y);
    __nv_bfloat16 h2 = __float2bfloat16(v.z), h3 = __float2bfloat16(v.w);
    __nv_bfloat16 l0 = __float2bfloat16(v.x - __bfloat162float(h0));
    __nv_bfloat16 l1 = __float2bfloat16(v.y - __bfloat162float(h1));
    __nv_bfloat16 l2 = __float2bfloat16(v.z - __bfloat162float(h2));
    __nv_bfloat16 l3 = __float2bfloat16(v.w - __bfloat162float(h3));
    __nv_bfloat162* dh = (__nv_bfloat162*)(g_Wbig + n * 2048 + k4 * 4);
    __nv_bfloat162* dl = (__nv_bfloat162*)(g_Wbig + n * 2048 + 1024 + k4 * 4);
    __nv_bfloat162 a; a.x = h0; a.y = h1; dh[0] = a;
    __nv_bfloat162 b; b.x = h2; b.y = h3; dh[1] = b;
    __nv_bfloat162 c; c.x = l0; c.y = l1; dl[0] = c;
    __nv_bfloat162 d; d.x = l2; d.y = l3; dl[1] = d;
}

// ---------------- fused pregate SGEMMs ----------------
__global__ void sgemm3_k(const float* __restrict__ enc_emb, const float* __restrict__ dec_emb,
                         const float* __restrict__ W0, const float* __restrict__ b0,
                         const float* __restrict__ W1, const float* __restrict__ b1,
                         const float* __restrict__ W2, const float* __restrict__ b2,
                         const int* __restrict__ ri_enc, const int* __restrict__ ri_dec,
                         float* __restrict__ C0, float* __restrict__ C1, float* __restrict__ C2)
{
    const int z = blockIdx.z;
    const float *A, *W, *bias; const int* rowidx; float* C;
    int M, N;
    if (z == 0)      { if (blockIdx.x >= 16) return; A = enc_emb; W = W0; bias = b0; rowidx = ri_enc; C = C0; M = S_ * B_;  N = GH; }
    else if (z == 1) { if (blockIdx.x >= 16) return; A = enc_emb; W = W1; bias = b1; rowidx = ri_enc; C = C1; M = S_ * B_;  N = GH; }
    else             { if (blockIdx.y >= 16) return; A = dec_emb; W = W2; bias = b2; rowidx = ri_dec; C = C2; M = TD * B_; N = DG; }
    const int K = E_;

    __shared__ float As[16][128];
    __shared__ float Bs[16][128];
    const int tid = threadIdx.x;
    const int m0 = blockIdx.y * 128, n0 = blockIdx.x * 128;
    const int lm = tid & 127, lq = tid >> 7;
    int mm = m0 + lm; if (mm >= M) mm = M - 1;
    const float* aptr = A + (size_t)rowidx[mm] * K;
    const float* bptr = W + (size_t)(n0 + lm) * K;
    const int tx = tid & 15, ty = tid >> 4;
    float acc[8][8];
#pragma unroll
    for (int i = 0; i < 8; i++)
#pragma unroll
        for (int j = 0; j < 8; j++) acc[i][j] = 0.f;

    for (int k0 = 0; k0 < K; k0 += 16) {
        float4 a0 = *(const float4*)(aptr + k0 + 4 * lq);
        float4 a1 = *(const float4*)(aptr + k0 + 4 * lq + 8);
        float4 b0v = *(const float4*)(bptr + k0 + 4 * lq);
        float4 b1v = *(const float4*)(bptr + k0 + 4 * lq + 8);
        __syncthreads();
        As[4 * lq + 0][lm] = a0.x; As[4 * lq + 1][lm] = a0.y;
        As[4 * lq + 2][lm] = a0.z; As[4 * lq + 3][lm] = a0.w;
        As[4 * lq + 8][lm] = a1.x; As[4 * lq + 9][lm] = a1.y;
        As[4 * lq + 10][lm] = a1.z; As[4 * lq + 11][lm] = a1.w;
        Bs[4 * lq + 0][lm] = b0v.x; Bs[4 * lq + 1][lm] = b0v.y;
        Bs[4 * lq + 2][lm] = b0v.z; Bs[4 * lq + 3][lm] = b0v.w;
        Bs[4 * lq + 8][lm] = b1v.x; Bs[4 * lq + 9][lm] = b1v.y;
        Bs[4 * lq + 10][lm] = b1v.z; Bs[4 * lq + 11][lm] = b1v.w;
        __syncthreads();
#pragma unroll
        for (int k = 0; k < 16; k++) {
            float ar[8], br[8];
            *(float4*)&ar[0] = *(const float4*)&As[k][ty * 8];
            *(float4*)&ar[4] = *(const float4*)&As[k][ty * 8 + 4];
            *(float4*)&br[0] = *(const float4*)&Bs[k][tx * 8];
            *(float4*)&br[4] = *(const float4*)&Bs[k][tx * 8 + 4];
#pragma unroll
            for (int i = 0; i < 8; i++)
#pragma unroll
                for (int j = 0; j < 8; j++) acc[i][j] += ar[i] * br[j];
        }
    }
#pragma unroll
    for (int i = 0; i < 8; i++) {
        int m = m0 + ty * 8 + i;
        if (m >= M) break;
        int t = m >> 5, b = m & 31;
        const float* bp = bias + n0 + tx * 8;
#pragma unroll
        for (int j = 0; j < 8; j++)
            C[((size_t)t * N + (n0 + tx * 8 + j)) * B_ + b] = acc[i][j] + bp[j];
    }
}

// ---------------- persistent encoder: f32x2 + pre-duplicated h pairs ----------------
// smem: sw_if 32KB | sw_go 32KB | shT2 h-pairs 128KB = 192KB
__global__ void enc_persist_k(const float* __restrict__ Whh_f,
                              const float* __restrict__ Whh_b)
{
    extern __shared__ float smemf[];
    float2* sw_if = (float2*)smemf;
    float2* sw_go = (float2*)(smemf + 8192);
    float*  shT2  = smemf + 16384;            // pairs: [k*B + b] each 8B
    const int dir = blockIdx.x >> 6, cb = blockIdx.x & 63;
    const int w = threadIdx.x >> 5, lane = threadIdx.x & 31;
    const int j = cb * 8 + w;
    const float* Whh = dir ? Whh_b : Whh_f;
    const float* preBase = dir ? g_pre_bT : g_pre_fT;
    unsigned* cnt = &g_sync[dir * 64];
    unsigned* gen = &g_sync[dir * 64 + 32];

    // stage interleaved weight pairs once
    {
        const int base_j = cb * 8;
        for (int idx = threadIdx.x; idx < 8 * H_; idx += 256) {
            int c = idx >> 9, k = idx & 511;
            float wi = Whh[(size_t)(0 * H_ + base_j + c) * H_ + k];
            float wf = Whh[(size_t)(1 * H_ + base_j + c) * H_ + k];
            float wg = Whh[(size_t)(2 * H_ + base_j + c) * H_ + k];
            float wo = Whh[(size_t)(3 * H_ + base_j + c) * H_ + k];
            sw_if[idx] = make_float2(wi, wf);
            sw_go[idx] = make_float2(wg, wo);
        }
    }
    __syncthreads();

    const ulonglong2* pif = (const ulonglong2*)(sw_if + (size_t)w * H_);
    const ulonglong2* pgo = (const ulonglong2*)(sw_go + (size_t)w * H_);
    const unsigned long long* hp = (const unsigned long long*)shT2;
    float cst = 0.f;

    for (int s = 0; s < S_; s++) {
        // stage h duplicated: element e -> pair (h,h) at shT2 + e*8
        {
            const float4* s4 = (const float4*)g_enc_hT[dir][s & 1];
            for (int i = threadIdx.x; i < H_ * B_ / 4; i += 256) {
                float4 v = __ldcg(s4 + i);
                float4* dst = (float4*)(shT2 + (size_t)i * 8);
                dst[0] = make_float4(v.x, v.x, v.y, v.y);
                dst[1] = make_float4(v.z, v.z, v.w, v.w);
            }
        }
        __syncthreads();
        const int t = dir ? (S_ - 1 - s) : s;
        const float* preT = preBase + (size_t)t * GH * B_;
        unsigned long long acc_if = pk2(__ldcg(preT + (size_t)(0 * H_ + j) * B_ + lane),
                                        __ldcg(preT + (size_t)(1 * H_ + j) * B_ + lane));
        unsigned long long acc_go = pk2(__ldcg(preT + (size_t)(2 * H_ + j) * B_ + lane),
                                        __ldcg(preT + (size_t)(3 * H_ + j) * B_ + lane));
#pragma unroll 4
        for (int k4 = 0; k4 < H_ / 4; k4++) {
            ulonglong2 a01 = pif[k4 * 2], a23 = pif[k4 * 2 + 1];
            ulonglong2 g01 = pgo[k4 * 2], g23 = pgo[k4 * 2 + 1];
            unsigned long long H0 = hp[(k4 * 4 + 0) * B_ + lane];
            unsigned long long H1 = hp[(k4 * 4 + 1) * B_ + lane];
            unsigned long long H2 = hp[(k4 * 4 + 2) * B_ + lane];
            unsigned long long H3 = hp[(k4 * 4 + 3) * B_ + lane];
            acc_if = ffma2(a01.x, H0, acc_if);
            acc_if = ffma2(a01.y, H1, acc_if);
            acc_if = ffma2(a23.x, H2, acc_if);
            acc_if = ffma2(a23.y, H3, acc_if);
            acc_go = ffma2(g01.x, H0, acc_go);
            acc_go = ffma2(g01.y, H1, acc_go);
            acc_go = ffma2(g23.x, H2, acc_go);
            acc_go = ffma2(g23.y, H3, acc_go);
        }
        float ai, af, ag, ao;
        unpk2(acc_if, ai, af);
        unpk2(acc_go, ag, ao);
        float iv = fsig(ai), fv = fsig(af), gv = ftanh(ag), ov = fsig(ao);
        cst = fv * cst + iv * gv;
        __stcg(&g_enc_hT[dir][(s + 1) & 1][(size_t)j * B_ + lane], ov * ftanh(cst));
        if (s == S_ - 1) g_enc_cT[dir][(size_t)j * B_ + lane] = cst;
        grid_barrier2(cnt, gen, (unsigned)(s + 1), 64u);
    }
}

// ---------------- persistent decoder: f32x2 + h pairs in 4 quarters ----------------
// smem: sw_if 64KB | sw_go 64KB | shQ h-pairs 64KB (256 k-values) = 192KB
__global__ void dec_persist_k(const float* __restrict__ Whh)
{
    extern __shared__ float smemf[];
    float2* sw_if = (float2*)smemf;
    float2* sw_go = (float2*)(smemf + 16384);
    float*  shQ   = smemf + 32768;            // pairs for one 256-k quarter
    const int w = threadIdx.x >> 5, lane = threadIdx.x & 31;
    const int j = blockIdx.x * 8 + w;
    unsigned* cnt = &g_sync[128];
    unsigned* gen = &g_sync[160];

    // stage interleaved weight pairs once
    {
        const int base_j = blockIdx.x * 8;
        for (int idx = threadIdx.x; idx < 8 * DH; idx += 256) {
            int c = idx >> 10, k = idx & 1023;
            float wi = Whh[(size_t)(0 * DH + base_j + c) * DH + k];
            float wf = Whh[(size_t)(1 * DH + base_j + c) * DH + k];
            float wg = Whh[(size_t)(2 * DH + base_j + c) * DH + k];
            float wo = Whh[(size_t)(3 * DH + base_j + c) * DH + k];
            sw_if[idx] = make_float2(wi, wf);
            sw_go[idx] = make_float2(wg, wo);
        }
    }

    float cst, h0v;
    if (j < H_) { cst = g_enc_cT[0][j * B_ + lane]; h0v = g_enc_hT[0][0][j * B_ + lane]; }
    else { cst = g_enc_cT[1][(j - H_) * B_ + lane]; h0v = g_enc_hT[1][0][(j - H_) * B_ + lane]; }
    __stcg(&g_dec_hT[0][(size_t)j * B_ + lane], h0v);
    grid_barrier2(cnt, gen, 1u, 128u);

    const ulonglong2* pifB = (const ulonglong2*)(sw_if + (size_t)w * DH);
    const ulonglong2* pgoB = (const ulonglong2*)(sw_go + (size_t)w * DH);
    const unsigned long long* hp = (const unsigned long long*)shQ;

    for (int t = 0; t < TD; t++) {
        const float* preT = g_dec_preT + (size_t)t * DG * B_;
        unsigned long long acc_if = pk2(__ldcg(preT + (size_t)(0 * DH + j) * B_ + lane),
                                        __ldcg(preT + (size_t)(1 * DH + j) * B_ + lane));
        unsigned long long acc_go = pk2(__ldcg(preT + (size_t)(2 * DH + j) * B_ + lane),
                                        __ldcg(preT + (size_t)(3 * DH + j) * B_ + lane));

#pragma unroll
        for (int q = 0; q < 4; q++) {
            // stage quarter q: k in [q*256, q*256+256), duplicated pairs
            {
                const float4* s4 = (const float4*)g_dec_hT[t & 1] + q * 2048;
                for (int i = threadIdx.x; i < 2048; i += 256) {
                    float4 v = __ldcg(s4 + i);
                    float4* dst = (float4*)(shQ + (size_t)i * 8);
                    dst[0] = make_float4(v.x, v.x, v.y, v.y);
                    dst[1] = make_float4(v.z, v.z, v.w, v.w);
                }
            }
            __syncthreads();
            const ulonglong2* pif = pifB + q * 128;
            const ulonglong2* pgo = pgoB + q * 128;
#pragma unroll 4
            for (int k4 = 0; k4 < 64; k4++) {
                ulonglong2 a01 = pif[k4 * 2], a23 = pif[k4 * 2 + 1];
                ulonglong2 g01 = pgo[k4 * 2], g23 = pgo[k4 * 2 + 1];
                unsigned long long H0 = hp[(k4 * 4 + 0) * B_ + lane];
                unsigned long long H1 = hp[(k4 * 4 + 1) * B_ + lane];
                unsigned long long H2 = hp[(k4 * 4 + 2) * B_ + lane];
                unsigned long long H3 = hp[(k4 * 4 + 3) * B_ + lane];
                acc_if = ffma2(a01.x, H0, acc_if);
                acc_if = ffma2(a01.y, H1, acc_if);
                acc_if = ffma2(a23.x, H2, acc_if);
                acc_if = ffma2(a23.y, H3, acc_if);
                acc_go = ffma2(g01.x, H0, acc_go);
                acc_go = ffma2(g01.y, H1, acc_go);
                acc_go = ffma2(g23.x, H2, acc_go);
                acc_go = ffma2(g23.y, H3, acc_go);
            }
            if (q < 3) __syncthreads();   // shQ reused next quarter; q=3 covered by barrier
        }

        float ai, af, ag, ao;
        unpk2(acc_if, ai, af);
        unpk2(acc_go, ag, ao);
        float iv = fsig(ai), fv = fsig(af), gv = ftanh(ag), ov = fsig(ao);
        cst = fv * cst + iv * gv;
        float hv = ov * ftanh(cst);
        __stcg(&g_dec_hT[(t + 1) & 1][(size_t)j * B_ + lane], hv);
        size_t m = (size_t)t * B_ + lane;
        __nv_bfloat16 hi = __float2bfloat16(hv);
        g_Abig[m * 2048 + j] = hi;
        g_Abig[m * 2048 + 1024 + j] = __float2bfloat16(hv - __bfloat162float(hi));
        grid_barrier2(cnt, gen, (unsigned)(t + 2), 128u);
    }
}

// ================= tcgen05 final GEMM (unchanged) =================
#define KCH    16
#define STAGE  98304
#define OFF_AHI0 0
#define OFF_AHI1 16384
#define OFF_ALO0 32768
#define OFF_ALO1 49152
#define OFF_WHI  65536
#define OFF_WLO  81920
#define SMEM_HDR 1024
#define SMEM_TC  (SMEM_HDR + 2 * STAGE)
#define IDESC_F16 ((1u<<4)|(1u<<7)|(1u<<10)|((128u/8)<<17)|((128u/16)<<24))

static __device__ __forceinline__ uint32_t swz(uint32_t x) { return x ^ ((x >> 3) & 0x70); }

__device__ __forceinline__ uint32_t smem_u32(const void* p)
{
    uint32_t a;
    asm("{ .reg .u64 t; cvta.to.shared.u64 t, %1; cvt.u32.u64 %0, t; }" : "=r"(a) : "l"(p));
    return a;
}
__device__ __forceinline__ void cp16(uint32_t dst, const void* src)
{
    asm volatile("cp.async.cg.shared.global [%0], [%1], 16;" :: "r"(dst), "l"(src));
}

#if HAS_TC
__device__ __forceinline__ uint32_t elect1()
{
    uint32_t p;
    asm volatile("{ .reg .pred p; elect.sync _|p, 0xFFFFFFFF; selp.b32 %0, 1, 0, p; }" : "=r"(p));
    return p;
}
__device__ __forceinline__ void mma_f16_ss(uint32_t d, uint64_t ad, uint64_t bd,
                                           uint32_t idesc, uint32_t en)
{
    asm volatile(
        "{\n\t.reg .pred p;\n\tsetp.ne.u32 p, %5, 0;\n\t"
        "tcgen05.mma.cta_group::1.kind::f16 [%0], %1, %2, %3, {%4,%4,%4,%4}, p;\n\t}"
        :: "r"(d), "l"(ad), "l"(bd), "r"(idesc), "r"(0u), "r"(en) : "memory");
}
#endif

__device__ __forceinline__ void load_chunk(const __nv_bfloat16* Ag, const __nv_bfloat16* Wg,
                                           int kc, uint32_t sbase, int tid)
{
    {
        const __nv_bfloat16* sA = Ag + (size_t)tid * 2048 + kc;
        uint32_t abase = sbase + ((tid < 128) ? OFF_AHI0 : OFF_AHI1);
        uint32_t lbase = sbase + ((tid < 128) ? OFF_ALO0 : OFF_ALO1);
        uint32_t r = (tid & 127) * 128;
#pragma unroll
        for (int g = 0; g < 8; g++) cp16(abase + swz(r + g * 16), sA + g * 8);
#pragma unroll
        for (int g = 0; g < 8; g++) cp16(lbase + swz(r + g * 16), sA + 1024 + g * 8);
    }
    {
        int rw = tid >> 1, g0 = (tid & 1) * 4;
        const __nv_bfloat16* sW = Wg + (size_t)rw * 2048 + kc + g0 * 8;
        uint32_t r = rw * 128 + g0 * 16;
#pragma unroll
        for (int g = 0; g < 4; g++) cp16(sbase + OFF_WHI + swz(r + g * 16), sW + g * 8);
#pragma unroll
        for (int g = 0; g < 4; g++) cp16(sbase + OFF_WLO + swz(r + g * 16), sW + 1024 + g * 8);
    }
    asm volatile("cp.async.commit_group;" ::: "memory");
}

__global__ __launch_bounds__(256, 1)
void bgemm_tc(const float* __restrict__ bias, float* __restrict__ out)
{
#if HAS_TC
    extern __shared__ __align__(1024) unsigned char sm[];
    const uint32_t sbase = smem_u32(sm);
    const int tid = threadIdx.x, wid = tid >> 5, lane = tid & 31;
    const int n0 = blockIdx.x * 128;
    const int m0g = blockIdx.y * 256;
    const __nv_bfloat16* Ag = g_Abig + (size_t)m0g * 2048;
    const __nv_bfloat16* Wg = g_Wbig + (size_t)n0 * 2048;

    if (wid == 0)
        asm volatile("tcgen05.alloc.cta_group::1.sync.aligned.shared::cta.b32 [%0], 512;"
                     :: "r"(sbase) : "memory");
    if (tid == 0) {
        asm volatile("mbarrier.init.shared.b64 [%0], 1;" :: "r"(sbase + 16) : "memory");
        asm volatile("mbarrier.init.shared.b64 [%0], 1;" :: "r"(sbase + 24) : "memory");
    }
    __syncthreads();
    uint32_t tmem;
    asm volatile("ld.shared.b32 %0, [%1];" : "=r"(tmem) : "r"(sbase));

    load_chunk(Ag, Wg, 0, sbase + SMEM_HDR, tid);
    load_chunk(Ag, Wg, 64, sbase + SMEM_HDR + STAGE, tid);

    int phase0 = 0, phase1 = 0;
    for (int c = 0; c < KCH; c++) {
        const int p = c & 1;
        if (c + 1 < KCH) asm volatile("cp.async.wait_group 1;" ::: "memory");
        else             asm volatile("cp.async.wait_group 0;" ::: "memory");
        __syncthreads();
        asm volatile("fence.proxy.async.shared::cta;" ::: "memory");

        if (wid == 0 && elect1()) {
            const uint32_t st = sbase + SMEM_HDR + p * STAGE;
            const uint64_t BASE = (uint64_t(2) << 61) | (uint64_t(1) << 46) |
                                  (uint64_t(64) << 32) | (uint64_t(1) << 16);
            uint64_t dAhi0 = BASE | (((st + OFF_AHI0) >> 4) & 0x3FFF);
            uint64_t dAhi1 = BASE | (((st + OFF_AHI1) >> 4) & 0x3FFF);
            uint64_t dAlo0 = BASE | (((st + OFF_ALO0) >> 4) & 0x3FFF);
            uint64_t dAlo1 = BASE | (((st + OFF_ALO1) >> 4) & 0x3FFF);
            uint64_t dWhi  = BASE | (((st + OFF_WHI) >> 4) & 0x3FFF);
            uint64_t dWlo  = BASE | (((st + OFF_WLO) >> 4) & 0x3FFF);
#pragma unroll
            for (int ks = 0; ks < 4; ks++) {
                uint32_t en0 = (c == 0 && ks == 0) ? 0u : 1u;
                mma_f16_ss(tmem + 0,   dAhi0 + ks * 2, dWhi + ks * 2, IDESC_F16, en0);
                mma_f16_ss(tmem + 128, dAhi1 + ks * 2, dWhi + ks * 2, IDESC_F16, en0);
                mma_f16_ss(tmem + 0,   dAhi0 + ks * 2, dWlo + ks * 2, IDESC_F16, 1u);
                mma_f16_ss(tmem + 128, dAhi1 + ks * 2, dWlo + ks * 2, IDESC_F16, 1u);
                mma_f16_ss(tmem + 0,   dAlo0 + ks * 2, dWhi + ks * 2, IDESC_F16, 1u);
                mma_f16_ss(tmem + 128, dAlo1 + ks * 2, dWhi + ks * 2, IDESC_F16, 1u);
            }
            asm volatile(
                "tcgen05.commit.cta_group::1.mbarrier::arrive::one.shared::cluster.b64 [%0];"
                :: "r"(sbase + 16 + p * 8) : "memory");
        }
        {
            uint32_t mb = sbase + 16 + p * 8;
            uint32_t ph = p ? phase1 : phase0;
            uint32_t done;
            asm volatile(
                "{\n\t.reg .pred q;\n\t"
                "mbarrier.try_wait.parity.shared.b64 q, [%1], %2, 0x989680;\n\t"
                "selp.b32 %0, 1, 0, q;\n\t}"
                : "=r"(done) : "r"(mb), "r"(ph) : "memory");
            while (!done) {
                asm volatile(
                    "{\n\t.reg .pred q;\n\t"
                    "mbarrier.try_wait.parity.shared.b64 q, [%1], %2, 0x989680;\n\t"
                    "selp.b32 %0, 1, 0, q;\n\t}"
                    : "=r"(done) : "r"(mb), "r"(ph) : "memory");
            }
            if (p) phase1 ^= 1; else phase0 ^= 1;
        }
        if (c + 2 < KCH)
            load_chunk(Ag, Wg, (c + 2) * 64, sbase + SMEM_HDR + p * STAGE, tid);
    }

    asm volatile("tcgen05.fence::after_thread_sync;" ::: "memory");
    {
        const int sub = tid >> 7;
        const int wiw = (tid >> 5) & 3;
        const int mrow = m0g + sub * 128 + wiw * 32 + lane;
        const uint32_t warp_off = ((uint32_t)(tid & 127) >> 5) << 21;
        const uint32_t dbase = tmem + sub * 128 + warp_off;
        if (mrow < MROWS) {
            const int t = mrow >> 5, b = mrow & 31;
            float* orow = out + (size_t)(b * T_ + t + 1) * V_ + n0;
#pragma unroll
            for (int q = 0; q < 4; q++) {
                uint32_t r[32];
                asm volatile(
                    "tcgen05.ld.sync.aligned.32x32b.x32.b32 "
                    "{%0,%1,%2,%3,%4,%5,%6,%7,%8,%9,%10,%11,%12,%13,%14,%15,"
                    "%16,%17,%18,%19,%20,%21,%22,%23,%24,%25,%26,%27,%28,%29,%30,%31}, [%32];"
                    : "=r"(r[0]), "=r"(r[1]), "=r"(r[2]), "=r"(r[3]), "=r"(r[4]), "=r"(r[5]),
                      "=r"(r[6]), "=r"(r[7]), "=r"(r[8]), "=r"(r[9]), "=r"(r[10]), "=r"(r[11]),
                      "=r"(r[12]), "=r"(r[13]), "=r"(r[14]), "=r"(r[15]), "=r"(r[16]), "=r"(r[17]),
                      "=r"(r[18]), "=r"(r[19]), "=r"(r[20]), "=r"(r[21]), "=r"(r[22]), "=r"(r[23]),
                      "=r"(r[24]), "=r"(r[25]), "=r"(r[26]), "=r"(r[27]), "=r"(r[28]), "=r"(r[29]),
                      "=r"(r[30]), "=r"(r[31])
                    : "r"(dbase + q * 32));
                asm volatile("tcgen05.wait::ld.sync.aligned;" ::: "memory");
#pragma unroll
                for (int c4 = 0; c4 < 8; c4++) {
                    const int n = q * 32 + c4 * 4;
                    float4 bb = *(const float4*)(bias + n0 + n);
                    float4 v;
                    v.x = __uint_as_float(r[c4 * 4 + 0]) + bb.x;
                    v.y = __uint_as_float(r[c4 * 4 + 1]) + bb.y;
                    v.z = __uint_as_float(r[c4 * 4 + 2]) + bb.z;
                    v.w = __uint_as_float(r[c4 * 4 + 3]) + bb.w;
                    *(float4*)(orow + n) = v;
                }
            }
        } else {
#pragma unroll
            for (int q = 0; q < 4; q++) {
                uint32_t r0;
                asm volatile("tcgen05.ld.sync.aligned.32x32b.x1.b32 {%0}, [%1];"
                             : "=r"(r0) : "r"(dbase + q * 32));
                asm volatile("tcgen05.wait::ld.sync.aligned;" ::: "memory");
            }
        }
    }
    __syncthreads();
    if (wid == 0) {
        asm volatile("tcgen05.relinquish_alloc_permit.cta_group::1.sync.aligned;" ::: "memory");
        asm volatile("tcgen05.dealloc.cta_group::1.sync.aligned.b32 %0, 512;" :: "r"(tmem));
    }
#endif  // HAS_TC
}

// ---------------- launch ----------------
extern "C" void kernel_launch(void* const* d_in, const int* in_sizes, int n_in,
                              void* d_out, int out_size)
{
    (void)in_sizes; (void)n_in; (void)out_size;
    const int*   src     = (const int*)d_in[0];
    const int*   trg     = (const int*)d_in[1];
    const float* enc_emb = (const float*)d_in[2];
    const float* dec_emb = (const float*)d_in[3];
    const float* eWih_f  = (const float*)d_in[4];
    const float* eWhh_f  = (const float*)d_in[5];
    const float* eb_f    = (const float*)d_in[6];
    const float* eWih_b  = (const float*)d_in[7];
    const float* eWhh_b  = (const float*)d_in[8];
    const float* eb_b    = (const float*)d_in[9];
    const float* dWih    = (const float*)d_in[10];
    const float* dWhh    = (const float*)d_in[11];
    const float* db      = (const float*)d_in[12];
    const float* fcW     = (const float*)d_in[13];
    const float* fcb     = (const float*)d_in[14];
    float* out = (float*)d_out;

    cudaFuncSetAttribute(enc_persist_k, cudaFuncAttributeMaxDynamicSharedMemorySize,
                         196608);                         // 192 KB
    cudaFuncSetAttribute(dec_persist_k, cudaFuncAttributeMaxDynamicSharedMemorySize,
                         196608);                         // 192 KB
    cudaFuncSetAttribute(bgemm_tc, cudaFuncAttributeMaxDynamicSharedMemorySize, SMEM_TC);

    void *p_pre_fT, *p_pre_bT, *p_dec_preT, *p_enc_ri, *p_dec_ri;
    cudaGetSymbolAddress(&p_pre_fT, g_pre_fT);
    cudaGetSymbolAddress(&p_pre_bT, g_pre_bT);
    cudaGetSymbolAddress(&p_dec_preT, g_dec_preT);
    cudaGetSymbolAddress(&p_enc_ri, g_enc_rowidx);
    cudaGetSymbolAddress(&p_dec_ri, g_dec_rowidx);

    long total = (long)B_ * V_ + 2L * H_ * B_ + (long)S_ * B_ + (long)TD * B_
               + 192 + (long)(MPAD - MROWS) * 2048;
    prep_k<<<(unsigned)((total + 255) / 256), 256>>>(src, trg, out);
    wconv_k<<<V_, 256>>>(fcW);

    sgemm3_k<<<dim3(32, 32, 3), 256>>>(
        enc_emb, dec_emb, eWih_f, eb_f, eWih_b, eb_b, dWih, db,
        (const int*)p_enc_ri, (const int*)p_dec_ri,
        (float*)p_pre_fT, (float*)p_pre_bT, (float*)p_dec_preT);

    enc_persist_k<<<128, 256, 196608>>>(eWhh_f, eWhh_b);
    dec_persist_k<<<128, 256, 196608>>>(dWhh);

    bgemm_tc<<<dim3(V_ / 128, MPAD / 256), 256, SMEM_TC>>>(fcb, out);
}

// round 13
// speedup vs baseline: 1.2768x; 1.2768x over previous
#include <cuda_runtime.h>
#include <cuda_bf16.h>
#include <math.h>
#include <stdint.h>

#define B_  32
#define S_  128
#define T_  64
#define E_  256
#define H_  512
#define V_  32000
#define GH  2048
#define DH  1024
#define DG  4096
#define TD  63
#define MROWS 2016
#define MPAD  2048

// tcgen05 only legal in the compute_103a feature pass.
#if defined(__CUDA_ARCH_FEAT_SM103_ALL) || defined(__CUDA_ARCH_FEAT_SM100_ALL) || !defined(__CUDA_ARCH__)
#define HAS_TC 1
#else
#define HAS_TC 0
#endif

// ---------------- scratch ----------------
__device__ float g_pre_fT[(size_t)S_ * GH * B_];
__device__ float g_pre_bT[(size_t)S_ * GH * B_];
__device__ float g_dec_preT[(size_t)TD * DG * B_];
__device__ float g_enc_hT[2][2][H_ * B_];
__device__ float g_enc_cT[2][H_ * B_];
__device__ float g_dec_hT[2][DH * B_];
__device__ int   g_enc_rowidx[S_ * B_];
__device__ int   g_dec_rowidx[TD * B_];
__device__ __nv_bfloat16 g_Abig[(size_t)MPAD * 2048];   // [hi(1024) | lo(1024)]
__device__ __nv_bfloat16 g_Wbig[(size_t)V_ * 2048];     // [hi | lo]
// pregate tensor operands: split-bf16, K=256 -> 512 (hi 256 | lo 256)
__device__ __nv_bfloat16 g_Wp[(size_t)8192 * 512];      // Wf(2048) | Wb(2048) | Wd(4096)
__device__ __nv_bfloat16 g_Aenc[(size_t)4096 * 512];
__device__ __nv_bfloat16 g_Adec[(size_t)2048 * 512];
__device__ unsigned g_sync[192];

// ---------------- grid barrier (R7/R9-proven: fence + acquire) ----------------
__device__ __forceinline__ void grid_barrier2(unsigned* cnt, unsigned* gen,
                                              unsigned step, unsigned nb)
{
    __syncthreads();
    if (threadIdx.x == 0) {
        __threadfence();
        unsigned old;
        asm volatile("atom.add.release.gpu.u32 %0, [%1], 1;"
                     : "=r"(old) : "l"(cnt) : "memory");
        if (old == step * nb - 1) {
            asm volatile("st.release.gpu.u32 [%0], %1;" :: "l"(gen), "r"(step) : "memory");
        } else {
            unsigned v;
            do {
                asm volatile("ld.acquire.gpu.u32 %0, [%1];" : "=r"(v) : "l"(gen) : "memory");
            } while (v < step);
        }
    }
    __syncthreads();
}

// ---------------- f32x2 packed helpers ----------------
__device__ __forceinline__ unsigned long long pk2(float lo, float hi)
{
    unsigned long long p;
    asm("mov.b64 %0, {%1, %2};" : "=l"(p) : "f"(lo), "f"(hi));
    return p;
}
__device__ __forceinline__ unsigned long long ffma2(unsigned long long a,
                                                    unsigned long long b,
                                                    unsigned long long c)
{
    unsigned long long d;
    asm("fma.rn.f32x2 %0, %1, %2, %3;" : "=l"(d) : "l"(a), "l"(b), "l"(c));
    return d;
}
__device__ __forceinline__ void unpk2(unsigned long long p, float& lo, float& hi)
{
    asm("mov.b64 {%0, %1}, %2;" : "=f"(lo), "=f"(hi) : "l"(p));
}

// ---------------- fast activations ----------------
__device__ __forceinline__ float fsig(float x)
{
    float e; asm("ex2.approx.f32 %0, %1;" : "=f"(e) : "f"(-1.4426950408889634f * x));
    float r; asm("rcp.approx.f32 %0, %1;" : "=f"(r) : "f"(1.f + e));
    return r;
}
__device__ __forceinline__ float ftanh(float x)
{
    float e; asm("ex2.approx.f32 %0, %1;" : "=f"(e) : "f"(2.8853900817779268f * x));
    float r; asm("rcp.approx.f32 %0, %1;" : "=f"(r) : "f"(1.f + e));
    return 1.f - 2.f * r;
}

// ---------------- prep ----------------
__global__ void prep_k(const int* __restrict__ src, const int* __restrict__ trg,
                       float* __restrict__ out)
{
    long idx = (long)blockIdx.x * blockDim.x + threadIdx.x;
    const long N0 = (long)B_ * V_;
    if (idx < N0) {
        long b = idx / V_, v = idx - b * V_;
        out[(size_t)b * T_ * V_ + v] = 0.f;
        return;
    }
    idx -= N0;
    if (idx < 2 * H_ * B_) { g_enc_hT[idx >> 14][0][idx & 16383] = 0.f; return; }
    idx -= 2 * H_ * B_;
    if (idx < S_ * B_) {
        int t = (int)(idx / B_), b = (int)(idx % B_);
        g_enc_rowidx[idx] = src[b * S_ + t];
        return;
    }
    idx -= S_ * B_;
    if (idx < TD * B_) {
        int t = (int)(idx / B_), b = (int)(idx % B_);
        g_dec_rowidx[idx] = trg[b * T_ + t];
        return;
    }
    idx -= TD * B_;
    if (idx < 192) { g_sync[idx] = 0; return; }
    idx -= 192;
    if (idx < (MPAD - MROWS) * 2048) {
        g_Abig[(size_t)(MROWS + (idx >> 11)) * 2048 + (idx & 2047)] = __float2bfloat16(0.f);
        return;
    }
}

// ---------------- split helper ----------------
__device__ __forceinline__ void split4(float4 v, __nv_bfloat16* hi, __nv_bfloat16* lo)
{
    hi[0] = __float2bfloat16(v.x); lo[0] = __float2bfloat16(v.x - __bfloat162float(hi[0]));
    hi[1] = __float2bfloat16(v.y); lo[1] = __float2bfloat16(v.y - __bfloat162float(hi[1]));
    hi[2] = __float2bfloat16(v.z); lo[2] = __float2bfloat16(v.z - __bfloat162float(hi[2]));
    hi[3] = __float2bfloat16(v.w); lo[3] = __float2bfloat16(v.w - __bfloat162float(hi[3]));
}

// ---------------- fcW split conversion (R9-proven geometry: 1024 floats/row) ----------
__global__ void wconv_k(const float* __restrict__ fcW)
{
    size_t i = (size_t)blockIdx.x * 256 + threadIdx.x;   // over V_*256 float4s
    if (i >= (size_t)V_ * 256) return;
    size_t n = i >> 8; int k4 = (int)(i & 255);
    float4 v = __ldcg((const float4*)fcW + i);
    __nv_bfloat16 hi[4], lo[4];
    split4(v, hi, lo);
    *(uint64_t*)(g_Wbig + n * 2048 + k4 * 4)        = *(uint64_t*)hi;
    *(uint64_t*)(g_Wbig + n * 2048 + 1024 + k4 * 4) = *(uint64_t*)lo;
}

// ---------------- Wih split conversion (all 3 matrices into g_Wp) ----------------
__global__ void pwconv_k(const float* __restrict__ Wf, const float* __restrict__ Wb,
                         const float* __restrict__ Wd)
{
    size_t i = (size_t)blockIdx.x * 256 + threadIdx.x;   // over 8192*64 float4s
    if (i >= (size_t)8192 * 64) return;
    size_t row = i >> 6; int k4 = (int)(i & 63);
    const float* src;
    size_t r = row;
    if (row < 2048)      src = Wf;
    else if (row < 4096) { src = Wb; r = row - 2048; }
    else                 { src = Wd; r = row - 4096; }
    float4 v = __ldcg((const float4*)(src + r * E_) + k4);
    __nv_bfloat16 hi[4], lo[4];
    split4(v, hi, lo);
    *(uint64_t*)(g_Wp + row * 512 + k4 * 4)       = *(uint64_t*)hi;
    *(uint64_t*)(g_Wp + row * 512 + 256 + k4 * 4) = *(uint64_t*)lo;
}

// ---------------- gathered-embedding split conversion ----------------
__global__ void paconv_k(const float* __restrict__ enc_emb, const float* __restrict__ dec_emb)
{
    size_t i = (size_t)blockIdx.x * 256 + threadIdx.x;   // over 6144*64 float4s
    if (i >= (size_t)6144 * 64) return;
    size_t row = i >> 6; int k4 = (int)(i & 63);
    __nv_bfloat16* dst;
    float4 v;
    if (row < 4096) {
        v = __ldcg((const float4*)(enc_emb + (size_t)g_enc_rowidx[row] * E_) + k4);
        dst = g_Aenc + row * 512;
    } else {
        size_t m = row - 4096;
        dst = g_Adec + m * 512;
        if (m < MROWS)
            v = __ldcg((const float4*)(dec_emb + (size_t)g_dec_rowidx[m] * E_) + k4);
        else
            v = make_float4(0.f, 0.f, 0.f, 0.f);
    }
    __nv_bfloat16 hi[4], lo[4];
    split4(v, hi, lo);
    *(uint64_t*)(dst + k4 * 4)       = *(uint64_t*)hi;
    *(uint64_t*)(dst + 256 + k4 * 4) = *(uint64_t*)lo;
}

// ================= shared tcgen05 GEMM plumbing =================
#define STAGE  98304
#define OFF_AHI0 0
#define OFF_AHI1 16384
#define OFF_ALO0 32768
#define OFF_ALO1 49152
#define OFF_WHI  65536
#define OFF_WLO  81920
#define SMEM_HDR 1024
#define SMEM_TC  (SMEM_HDR + 2 * STAGE)
#define IDESC_F16 ((1u<<4)|(1u<<7)|(1u<<10)|((128u/8)<<17)|((128u/16)<<24))

static __device__ __forceinline__ uint32_t swz(uint32_t x) { return x ^ ((x >> 3) & 0x70); }

__device__ __forceinline__ uint32_t smem_u32(const void* p)
{
    uint32_t a;
    asm("{ .reg .u64 t; cvta.to.shared.u64 t, %1; cvt.u32.u64 %0, t; }" : "=r"(a) : "l"(p));
    return a;
}
__device__ __forceinline__ void cp16(uint32_t dst, const void* src)
{
    asm volatile("cp.async.cg.shared.global [%0], [%1], 16;" :: "r"(dst), "l"(src));
}

#if HAS_TC
__device__ __forceinline__ uint32_t elect1()
{
    uint32_t p;
    asm volatile("{ .reg .pred p; elect.sync _|p, 0xFFFFFFFF; selp.b32 %0, 1, 0, p; }" : "=r"(p));
    return p;
}
__device__ __forceinline__ void mma_f16_ss(uint32_t d, uint64_t ad, uint64_t bd,
                                           uint32_t idesc, uint32_t en)
{
    asm volatile(
        "{\n\t.reg .pred p;\n\tsetp.ne.u32 p, %5, 0;\n\t"
        "tcgen05.mma.cta_group::1.kind::f16 [%0], %1, %2, %3, {%4,%4,%4,%4}, p;\n\t}"
        :: "r"(d), "l"(ad), "l"(bd), "r"(idesc), "r"(0u), "r"(en) : "memory");
}

// generic chunk loader: RS = A/W row stride in bf16 elems, LOFF = lo-half offset
template <int RS, int LOFF>
__device__ __forceinline__ void load_chunk_g(const __nv_bfloat16* Ag, const __nv_bfloat16* Wg,
                                             int kc, uint32_t sbase, int tid)
{
    {
        const __nv_bfloat16* sA = Ag + (size_t)tid * RS + kc;
        uint32_t abase = sbase + ((tid < 128) ? OFF_AHI0 : OFF_AHI1);
        uint32_t lbase = sbase + ((tid < 128) ? OFF_ALO0 : OFF_ALO1);
        uint32_t r = (tid & 127) * 128;
#pragma unroll
        for (int g = 0; g < 8; g++) cp16(abase + swz(r + g * 16), sA + g * 8);
#pragma unroll
        for (int g = 0; g < 8; g++) cp16(lbase + swz(r + g * 16), sA + LOFF + g * 8);
    }
    {
        int rw = tid >> 1, g0 = (tid & 1) * 4;
        const __nv_bfloat16* sW = Wg + (size_t)rw * RS + kc + g0 * 8;
        uint32_t r = rw * 128 + g0 * 16;
#pragma unroll
        for (int g = 0; g < 4; g++) cp16(sbase + OFF_WHI + swz(r + g * 16), sW + g * 8);
#pragma unroll
        for (int g = 0; g < 4; g++) cp16(sbase + OFF_WLO + swz(r + g * 16), sW + LOFF + g * 8);
    }
    asm volatile("cp.async.commit_group;" ::: "memory");
}

// MMA + pipeline body shared by both GEMMs
template <int RS, int LOFF, int KCHN>
__device__ __forceinline__ uint32_t tc_mainloop(const __nv_bfloat16* Ag,
                                                const __nv_bfloat16* Wg,
                                                uint32_t sbase, int tid, int wid)
{
    if (wid == 0)
        asm volatile("tcgen05.alloc.cta_group::1.sync.aligned.shared::cta.b32 [%0], 512;"
                     :: "r"(sbase) : "memory");
    if (tid == 0) {
        asm volatile("mbarrier.init.shared.b64 [%0], 1;" :: "r"(sbase + 16) : "memory");
        asm volatile("mbarrier.init.shared.b64 [%0], 1;" :: "r"(sbase + 24) : "memory");
    }
    __syncthreads();
    uint32_t tmem;
    asm volatile("ld.shared.b32 %0, [%1];" : "=r"(tmem) : "r"(sbase));

    load_chunk_g<RS, LOFF>(Ag, Wg, 0, sbase + SMEM_HDR, tid);
    if (KCHN > 1) load_chunk_g<RS, LOFF>(Ag, Wg, 64, sbase + SMEM_HDR + STAGE, tid);

    int phase0 = 0, phase1 = 0;
    for (int c = 0; c < KCHN; c++) {
        const int p = c & 1;
        if (c + 1 < KCHN) asm volatile("cp.async.wait_group 1;" ::: "memory");
        else              asm volatile("cp.async.wait_group 0;" ::: "memory");
        __syncthreads();
        asm volatile("fence.proxy.async.shared::cta;" ::: "memory");

        if (wid == 0 && elect1()) {
            const uint32_t st = sbase + SMEM_HDR + p * STAGE;
            const uint64_t BASE = (uint64_t(2) << 61) | (uint64_t(1) << 46) |
                                  (uint64_t(64) << 32) | (uint64_t(1) << 16);
            uint64_t dAhi0 = BASE | (((st + OFF_AHI0) >> 4) & 0x3FFF);
            uint64_t dAhi1 = BASE | (((st + OFF_AHI1) >> 4) & 0x3FFF);
            uint64_t dAlo0 = BASE | (((st + OFF_ALO0) >> 4) & 0x3FFF);
            uint64_t dAlo1 = BASE | (((st + OFF_ALO1) >> 4) & 0x3FFF);
            uint64_t dWhi  = BASE | (((st + OFF_WHI) >> 4) & 0x3FFF);
            uint64_t dWlo  = BASE | (((st + OFF_WLO) >> 4) & 0x3FFF);
#pragma unroll
            for (int ks = 0; ks < 4; ks++) {
                uint32_t en0 = (c == 0 && ks == 0) ? 0u : 1u;
                mma_f16_ss(tmem + 0,   dAhi0 + ks * 2, dWhi + ks * 2, IDESC_F16, en0);
                mma_f16_ss(tmem + 128, dAhi1 + ks * 2, dWhi + ks * 2, IDESC_F16, en0);
                mma_f16_ss(tmem + 0,   dAhi0 + ks * 2, dWlo + ks * 2, IDESC_F16, 1u);
                mma_f16_ss(tmem + 128, dAhi1 + ks * 2, dWlo + ks * 2, IDESC_F16, 1u);
                mma_f16_ss(tmem + 0,   dAlo0 + ks * 2, dWhi + ks * 2, IDESC_F16, 1u);
                mma_f16_ss(tmem + 128, dAlo1 + ks * 2, dWhi + ks * 2, IDESC_F16, 1u);
            }
            asm volatile(
                "tcgen05.commit.cta_group::1.mbarrier::arrive::one.shared::cluster.b64 [%0];"
                :: "r"(sbase + 16 + p * 8) : "memory");
        }
        {
            uint32_t mb = sbase + 16 + p * 8;
            uint32_t ph = p ? phase1 : phase0;
            uint32_t done;
            do {
                asm volatile(
                    "{\n\t.reg .pred q;\n\t"
                    "mbarrier.try_wait.parity.shared.b64 q, [%1], %2, 0x989680;\n\t"
                    "selp.b32 %0, 1, 0, q;\n\t}"
                    : "=r"(done) : "r"(mb), "r"(ph) : "memory");
            } while (!done);
            if (p) phase1 ^= 1; else phase0 ^= 1;
        }
        if (c + 2 < KCHN)
            load_chunk_g<RS, LOFF>(Ag, Wg, (c + 2) * 64, sbase + SMEM_HDR + p * STAGE, tid);
    }
    asm volatile("tcgen05.fence::after_thread_sync;" ::: "memory");
    return tmem;
}

#define LDTM32(r, addr) \
    asm volatile( \
        "tcgen05.ld.sync.aligned.32x32b.x32.b32 " \
        "{%0,%1,%2,%3,%4,%5,%6,%7,%8,%9,%10,%11,%12,%13,%14,%15," \
        "%16,%17,%18,%19,%20,%21,%22,%23,%24,%25,%26,%27,%28,%29,%30,%31}, [%32];" \
        : "=r"((r)[0]), "=r"((r)[1]), "=r"((r)[2]), "=r"((r)[3]), "=r"((r)[4]), "=r"((r)[5]), \
          "=r"((r)[6]), "=r"((r)[7]), "=r"((r)[8]), "=r"((r)[9]), "=r"((r)[10]), "=r"((r)[11]), \
          "=r"((r)[12]), "=r"((r)[13]), "=r"((r)[14]), "=r"((r)[15]), "=r"((r)[16]), "=r"((r)[17]), \
          "=r"((r)[18]), "=r"((r)[19]), "=r"((r)[20]), "=r"((r)[21]), "=r"((r)[22]), "=r"((r)[23]), \
          "=r"((r)[24]), "=r"((r)[25]), "=r"((r)[26]), "=r"((r)[27]), "=r"((r)[28]), "=r"((r)[29]), \
          "=r"((r)[30]), "=r"((r)[31]) \
        : "r"(addr))
#endif  // HAS_TC

// ---------------- final logits GEMM ----------------
__global__ __launch_bounds__(256, 1)
void bgemm_tc(const float* __restrict__ bias, float* __restrict__ out)
{
#if HAS_TC
    extern __shared__ __align__(1024) unsigned char sm[];
    const uint32_t sbase = smem_u32(sm);
    const int tid = threadIdx.x, wid = tid >> 5, lane = tid & 31;
    const int n0 = blockIdx.x * 128;
    const int m0g = blockIdx.y * 256;
    const __nv_bfloat16* Ag = g_Abig + (size_t)m0g * 2048;
    const __nv_bfloat16* Wg = g_Wbig + (size_t)n0 * 2048;

    uint32_t tmem = tc_mainloop<2048, 1024, 16>(Ag, Wg, sbase, tid, wid);

    {
        const int sub = tid >> 7;
        const int wiw = (tid >> 5) & 3;
        const int mrow = m0g + sub * 128 + wiw * 32 + lane;
        const uint32_t warp_off = ((uint32_t)(tid & 127) >> 5) << 21;
        const uint32_t dbase = tmem + sub * 128 + warp_off;
        const bool valid = mrow < MROWS;
        const int t = mrow >> 5, b = mrow & 31;
        float* orow = out + (size_t)(b * T_ + t + 1) * V_ + n0;
#pragma unroll
        for (int q = 0; q < 4; q++) {
            uint32_t r[32];
            LDTM32(r, dbase + q * 32);
            asm volatile("tcgen05.wait::ld.sync.aligned;" ::: "memory");
            if (valid) {
#pragma unroll
                for (int c4 = 0; c4 < 8; c4++) {
                    const int n = q * 32 + c4 * 4;
                    float4 bb = *(const float4*)(bias + n0 + n);
                    float4 v;
                    v.x = __uint_as_float(r[c4 * 4 + 0]) + bb.x;
                    v.y = __uint_as_float(r[c4 * 4 + 1]) + bb.y;
                    v.z = __uint_as_float(r[c4 * 4 + 2]) + bb.z;
                    v.w = __uint_as_float(r[c4 * 4 + 3]) + bb.w;
                    *(float4*)(orow + n) = v;
                }
            }
        }
    }
    __syncthreads();
    if (wid == 0) {
        asm volatile("tcgen05.relinquish_alloc_permit.cta_group::1.sync.aligned;" ::: "memory");
        asm volatile("tcgen05.dealloc.cta_group::1.sync.aligned.b32 %0, 512;" :: "r"(tmem));
    }
#endif
}

// ---------------- pregate GEMM (tensor): C[(t*Ntot+n)*32+b] = A@W^T + bias ----------------
__global__ __launch_bounds__(256, 1)
void pgemm_tc(const __nv_bfloat16* __restrict__ A, const __nv_bfloat16* __restrict__ W,
              const float* __restrict__ bias, float* __restrict__ C,
              int Ntot, int Mvalid)
{
#if HAS_TC
    extern __shared__ __align__(1024) unsigned char sm[];
    const uint32_t sbase = smem_u32(sm);
    const int tid = threadIdx.x, wid = tid >> 5, lane = tid & 31;
    const int n0 = blockIdx.x * 128;
    const int m0g = blockIdx.y * 256;
    const __nv_bfloat16* Ag = A + (size_t)m0g * 512;
    const __nv_bfloat16* Wg = W + (size_t)n0 * 512;

    uint32_t tmem = tc_mainloop<512, 256, 4>(Ag, Wg, sbase, tid, wid);

    {
        const int sub = tid >> 7;
        const int wiw = (tid >> 5) & 3;
        const int mrow = m0g + sub * 128 + wiw * 32 + lane;
        const uint32_t warp_off = ((uint32_t)(tid & 127) >> 5) << 21;
        const uint32_t dbase = tmem + sub * 128 + warp_off;
        const bool valid = mrow < Mvalid;
        const int t = mrow >> 5, b = mrow & 31;
#pragma unroll
        for (int q = 0; q < 4; q++) {
            uint32_t r[32];
            LDTM32(r, dbase + q * 32);
            asm volatile("tcgen05.wait::ld.sync.aligned;" ::: "memory");
            if (valid) {
#pragma unroll
                for (int c1 = 0; c1 < 32; c1++) {
                    const int n = n0 + q * 32 + c1;
                    C[((size_t)t * Ntot + n) * B_ + b] = __uint_as_float(r[c1]) + bias[n];
                }
            }
        }
    }
    __syncthreads();
    if (wid == 0) {
        asm volatile("tcgen05.relinquish_alloc_permit.cta_group::1.sync.aligned;" ::: "memory");
        asm volatile("tcgen05.dealloc.cta_group::1.sync.aligned.b32 %0, 512;" :: "r"(tmem));
    }
#endif
}

// ---------------- persistent encoder (R10-proven) ----------------
__global__ void enc_persist_k(const float* __restrict__ Whh_f,
                              const float* __restrict__ Whh_b)
{
    extern __shared__ float smemf[];
    float2* sw_if = (float2*)smemf;
    float2* sw_go = (float2*)(smemf + 8192);
    float*  shT   = smemf + 16384;
    const int dir = blockIdx.x >> 6, cb = blockIdx.x & 63;
    const int w = threadIdx.x >> 5, lane = threadIdx.x & 31;
    const int j = cb * 8 + w;
    const float* Whh = dir ? Whh_b : Whh_f;
    const float* preBase = dir ? g_pre_bT : g_pre_fT;
    unsigned* cnt = &g_sync[dir * 64];
    unsigned* gen = &g_sync[dir * 64 + 32];

    {
        const int base_j = cb * 8;
        for (int idx = threadIdx.x; idx < 8 * H_; idx += 256) {
            int c = idx >> 9, k = idx & 511;
            float wi = Whh[(size_t)(0 * H_ + base_j + c) * H_ + k];
            float wf = Whh[(size_t)(1 * H_ + base_j + c) * H_ + k];
            float wg = Whh[(size_t)(2 * H_ + base_j + c) * H_ + k];
            float wo = Whh[(size_t)(3 * H_ + base_j + c) * H_ + k];
            sw_if[idx] = make_float2(wi, wf);
            sw_go[idx] = make_float2(wg, wo);
        }
    }
    __syncthreads();

    const ulonglong2* pif = (const ulonglong2*)(sw_if + (size_t)w * H_);
    const ulonglong2* pgo = (const ulonglong2*)(sw_go + (size_t)w * H_);
    float cst = 0.f;

    for (int s = 0; s < S_; s++) {
        const float4* s4 = (const float4*)g_enc_hT[dir][s & 1];
        float4* d4 = (float4*)shT;
        for (int i = threadIdx.x; i < H_ * B_ / 4; i += 256) d4[i] = __ldcg(s4 + i);
        __syncthreads();
        const int t = dir ? (S_ - 1 - s) : s;
        const float* preT = preBase + (size_t)t * GH * B_;
        unsigned long long acc_if = pk2(__ldcg(preT + (size_t)(0 * H_ + j) * B_ + lane),
                                        __ldcg(preT + (size_t)(1 * H_ + j) * B_ + lane));
        unsigned long long acc_go = pk2(__ldcg(preT + (size_t)(2 * H_ + j) * B_ + lane),
                                        __ldcg(preT + (size_t)(3 * H_ + j) * B_ + lane));
#pragma unroll 4
        for (int k4 = 0; k4 < H_ / 4; k4++) {
            ulonglong2 a01 = pif[k4 * 2], a23 = pif[k4 * 2 + 1];
            ulonglong2 g01 = pgo[k4 * 2], g23 = pgo[k4 * 2 + 1];
            float h0 = shT[(k4 * 4 + 0) * B_ + lane];
            float h1 = shT[(k4 * 4 + 1) * B_ + lane];
            float h2 = shT[(k4 * 4 + 2) * B_ + lane];
            float h3 = shT[(k4 * 4 + 3) * B_ + lane];
            unsigned long long H0 = pk2(h0, h0), H1 = pk2(h1, h1);
            unsigned long long H2 = pk2(h2, h2), H3 = pk2(h3, h3);
            acc_if = ffma2(a01.x, H0, acc_if);
            acc_if = ffma2(a01.y, H1, acc_if);
            acc_if = ffma2(a23.x, H2, acc_if);
            acc_if = ffma2(a23.y, H3, acc_if);
            acc_go = ffma2(g01.x, H0, acc_go);
            acc_go = ffma2(g01.y, H1, acc_go);
            acc_go = ffma2(g23.x, H2, acc_go);
            acc_go = ffma2(g23.y, H3, acc_go);
        }
        float ai, af, ag, ao;
        unpk2(acc_if, ai, af);
        unpk2(acc_go, ag, ao);
        float iv = fsig(ai), fv = fsig(af), gv = ftanh(ag), ov = fsig(ao);
        cst = fv * cst + iv * gv;
        __stcg(&g_enc_hT[dir][(s + 1) & 1][(size_t)j * B_ + lane], ov * ftanh(cst));
        if (s == S_ - 1) g_enc_cT[dir][(size_t)j * B_ + lane] = cst;
        grid_barrier2(cnt, gen, (unsigned)(s + 1), 64u);
    }
}

// ---------------- persistent decoder (R10-proven) ----------------
__global__ void dec_persist_k(const float* __restrict__ Whh)
{
    extern __shared__ float smemf[];
    float2* sw_if = (float2*)smemf;
    float2* sw_go = (float2*)(smemf + 16384);
    float*  shH   = smemf + 32768;
    const int w = threadIdx.x >> 5, lane = threadIdx.x & 31;
    const int j = blockIdx.x * 8 + w;
    unsigned* cnt = &g_sync[128];
    unsigned* gen = &g_sync[160];

    {
        const int base_j = blockIdx.x * 8;
        for (int idx = threadIdx.x; idx < 8 * DH; idx += 256) {
            int c = idx >> 10, k = idx & 1023;
            float wi = Whh[(size_t)(0 * DH + base_j + c) * DH + k];
            float wf = Whh[(size_t)(1 * DH + base_j + c) * DH + k];
            float wg = Whh[(size_t)(2 * DH + base_j + c) * DH + k];
            float wo = Whh[(size_t)(3 * DH + base_j + c) * DH + k];
            sw_if[idx] = make_float2(wi, wf);
            sw_go[idx] = make_float2(wg, wo);
        }
    }

    float cst, h0v;
    if (j < H_) { cst = g_enc_cT[0][j * B_ + lane]; h0v = g_enc_hT[0][0][j * B_ + lane]; }
    else { cst = g_enc_cT[1][(j - H_) * B_ + lane]; h0v = g_enc_hT[1][0][(j - H_) * B_ + lane]; }
    __stcg(&g_dec_hT[0][(size_t)j * B_ + lane], h0v);
    grid_barrier2(cnt, gen, 1u, 128u);

    for (int t = 0; t < TD; t++) {
        const float* preT = g_dec_preT + (size_t)t * DG * B_;
        unsigned long long acc_if = pk2(__ldcg(preT + (size_t)(0 * DH + j) * B_ + lane),
                                        __ldcg(preT + (size_t)(1 * DH + j) * B_ + lane));
        unsigned long long acc_go = pk2(__ldcg(preT + (size_t)(2 * DH + j) * B_ + lane),
                                        __ldcg(preT + (size_t)(3 * DH + j) * B_ + lane));

#pragma unroll
        for (int half = 0; half < 2; half++) {
            const float4* s4 = (const float4*)g_dec_hT[t & 1] + half * 4096;
            float4* d4 = (float4*)shH;
            for (int i = threadIdx.x; i < 4096; i += 256) d4[i] = __ldcg(s4 + i);
            __syncthreads();
            const ulonglong2* pif =
                (const ulonglong2*)(sw_if + (size_t)w * DH) + half * 256;
            const ulonglong2* pgo =
                (const ulonglong2*)(sw_go + (size_t)w * DH) + half * 256;
#pragma unroll 4
            for (int k4 = 0; k4 < 128; k4++) {
                ulonglong2 a01 = pif[k4 * 2], a23 = pif[k4 * 2 + 1];
                ulonglong2 g01 = pgo[k4 * 2], g23 = pgo[k4 * 2 + 1];
                float h0 = shH[(k4 * 4 + 0) * B_ + lane];
                float h1 = shH[(k4 * 4 + 1) * B_ + lane];
                float h2 = shH[(k4 * 4 + 2) * B_ + lane];
                float h3 = shH[(k4 * 4 + 3) * B_ + lane];
                unsigned long long H0 = pk2(h0, h0), H1 = pk2(h1, h1);
                unsigned long long H2 = pk2(h2, h2), H3 = pk2(h3, h3);
                acc_if = ffma2(a01.x, H0, acc_if);
                acc_if = ffma2(a01.y, H1, acc_if);
                acc_if = ffma2(a23.x, H2, acc_if);
                acc_if = ffma2(a23.y, H3, acc_if);
                acc_go = ffma2(g01.x, H0, acc_go);
                acc_go = ffma2(g01.y, H1, acc_go);
                acc_go = ffma2(g23.x, H2, acc_go);
                acc_go = ffma2(g23.y, H3, acc_go);
            }
            if (half == 0) __syncthreads();
        }

        float ai, af, ag, ao;
        unpk2(acc_if, ai, af);
        unpk2(acc_go, ag, ao);
        float iv = fsig(ai), fv = fsig(af), gv = ftanh(ag), ov = fsig(ao);
        cst = fv * cst + iv * gv;
        float hv = ov * ftanh(cst);
        __stcg(&g_dec_hT[(t + 1) & 1][(size_t)j * B_ + lane], hv);
        size_t m = (size_t)t * B_ + lane;
        __nv_bfloat16 hi = __float2bfloat16(hv);
        g_Abig[m * 2048 + j] = hi;
        g_Abig[m * 2048 + 1024 + j] = __float2bfloat16(hv - __bfloat162float(hi));
        grid_barrier2(cnt, gen, (unsigned)(t + 2), 128u);
    }
}

// ---------------- launch ----------------
extern "C" void kernel_launch(void* const* d_in, const int* in_sizes, int n_in,
                              void* d_out, int out_size)
{
    (void)in_sizes; (void)n_in; (void)out_size;
    const int*   src     = (const int*)d_in[0];
    const int*   trg     = (const int*)d_in[1];
    const float* enc_emb = (const float*)d_in[2];
    const float* dec_emb = (const float*)d_in[3];
    const float* eWih_f  = (const float*)d_in[4];
    const float* eWhh_f  = (const float*)d_in[5];
    const float* eb_f    = (const float*)d_in[6];
    const float* eWih_b  = (const float*)d_in[7];
    const float* eWhh_b  = (const float*)d_in[8];
    const float* eb_b    = (const float*)d_in[9];
    const float* dWih    = (const float*)d_in[10];
    const float* dWhh    = (const float*)d_in[11];
    const float* db      = (const float*)d_in[12];
    const float* fcW     = (const float*)d_in[13];
    const float* fcb     = (const float*)d_in[14];
    float* out = (float*)d_out;

    cudaFuncSetAttribute(enc_persist_k, cudaFuncAttributeMaxDynamicSharedMemorySize, 131072);
    cudaFuncSetAttribute(dec_persist_k, cudaFuncAttributeMaxDynamicSharedMemorySize, 196608);
    cudaFuncSetAttribute(bgemm_tc, cudaFuncAttributeMaxDynamicSharedMemorySize, SMEM_TC);
    cudaFuncSetAttribute(pgemm_tc, cudaFuncAttributeMaxDynamicSharedMemorySize, SMEM_TC);

    void *p_pre_fT, *p_pre_bT, *p_dec_preT, *p_Wp, *p_Aenc, *p_Adec;
    cudaGetSymbolAddress(&p_pre_fT, g_pre_fT);
    cudaGetSymbolAddress(&p_pre_bT, g_pre_bT);
    cudaGetSymbolAddress(&p_dec_preT, g_dec_preT);
    cudaGetSymbolAddress(&p_Wp, g_Wp);
    cudaGetSymbolAddress(&p_Aenc, g_Aenc);
    cudaGetSymbolAddress(&p_Adec, g_Adec);
    __nv_bfloat16* Wp = (__nv_bfloat16*)p_Wp;

    long total = (long)B_ * V_ + 2L * H_ * B_ + (long)S_ * B_ + (long)TD * B_
               + 192 + (long)(MPAD - MROWS) * 2048;
    prep_k<<<(unsigned)((total + 255) / 256), 256>>>(src, trg, out);
    wconv_k<<<V_, 256>>>(fcW);
    pwconv_k<<<2048, 256>>>(eWih_f, eWih_b, dWih);
    paconv_k<<<1536, 256>>>(enc_emb, dec_emb);

    pgemm_tc<<<dim3(16, 16), 256, SMEM_TC>>>(
        (const __nv_bfloat16*)p_Aenc, Wp, eb_f, (float*)p_pre_fT, GH, 4096);
    pgemm_tc<<<dim3(16, 16), 256, SMEM_TC>>>(
        (const __nv_bfloat16*)p_Aenc, Wp + (size_t)2048 * 512, eb_b, (float*)p_pre_bT, GH, 4096);
    pgemm_tc<<<dim3(32, 8), 256, SMEM_TC>>>(
        (const __nv_bfloat16*)p_Adec, Wp + (size_t)4096 * 512, db, (float*)p_dec_preT, DG, MROWS);

    enc_persist_k<<<128, 256, 131072>>>(eWhh_f, eWhh_b);
    dec_persist_k<<<128, 256, 196608>>>(dWhh);

    bgemm_tc<<<dim3(V_ / 128, MPAD / 256), 256, SMEM_TC>>>(fcb, out);
}

// round 14
// speedup vs baseline: 1.4817x; 1.1604x over previous
#include <cuda_runtime.h>
#include <cuda_bf16.h>
#include <math.h>
#include <stdint.h>

#define B_  32
#define S_  128
#define T_  64
#define E_  256
#define H_  512
#define V_  32000
#define GH  2048
#define DH  1024
#define DG  4096
#define TD  63
#define MROWS 2016
#define MPAD  2048

// tcgen05 only legal in the compute_103a feature pass.
#if defined(__CUDA_ARCH_FEAT_SM103_ALL) || defined(__CUDA_ARCH_FEAT_SM100_ALL) || !defined(__CUDA_ARCH__)
#define HAS_TC 1
#else
#define HAS_TC 0
#endif

// ---------------- scratch ----------------
__device__ float g_pre_fT[(size_t)S_ * GH * B_];
__device__ float g_pre_bT[(size_t)S_ * GH * B_];
__device__ float g_dec_preT[(size_t)TD * DG * B_];
__device__ float g_enc_hT[2][2][H_ * B_];
__device__ float g_enc_cT[2][H_ * B_];
__device__ float g_dec_hT[2][DH * B_];
__device__ int   g_enc_rowidx[S_ * B_];
__device__ int   g_dec_rowidx[TD * B_];
__device__ __nv_bfloat16 g_Abig[(size_t)MPAD * 2048];   // [hi(1024) | lo(1024)]
__device__ __nv_bfloat16 g_Wbig[(size_t)V_ * 2048];     // [hi | lo]
// pregate tensor operands: split-bf16, K=256 -> 512 (hi 256 | lo 256)
__device__ __nv_bfloat16 g_Wp[(size_t)8192 * 512];      // Wf(2048) | Wb(2048) | Wd(4096)
__device__ __nv_bfloat16 g_Aenc[(size_t)4096 * 512];
__device__ __nv_bfloat16 g_Adec[(size_t)2048 * 512];
__device__ unsigned g_sync[192];

// ---------------- grid barrier (R7/R9-proven: fence + acquire) ----------------
__device__ __forceinline__ void grid_barrier2(unsigned* cnt, unsigned* gen,
                                              unsigned step, unsigned nb)
{
    __syncthreads();
    if (threadIdx.x == 0) {
        __threadfence();
        unsigned old;
        asm volatile("atom.add.release.gpu.u32 %0, [%1], 1;"
                     : "=r"(old) : "l"(cnt) : "memory");
        if (old == step * nb - 1) {
            asm volatile("st.release.gpu.u32 [%0], %1;" :: "l"(gen), "r"(step) : "memory");
        } else {
            unsigned v;
            do {
                asm volatile("ld.acquire.gpu.u32 %0, [%1];" : "=r"(v) : "l"(gen) : "memory");
            } while (v < step);
        }
    }
    __syncthreads();
}

// ---------------- f32x2 packed helpers ----------------
__device__ __forceinline__ unsigned long long pk2(float lo, float hi)
{
    unsigned long long p;
    asm("mov.b64 %0, {%1, %2};" : "=l"(p) : "f"(lo), "f"(hi));
    return p;
}
__device__ __forceinline__ unsigned long long ffma2(unsigned long long a,
                                                    unsigned long long b,
                                                    unsigned long long c)
{
    unsigned long long d;
    asm("fma.rn.f32x2 %0, %1, %2, %3;" : "=l"(d) : "l"(a), "l"(b), "l"(c));
    return d;
}
__device__ __forceinline__ void unpk2(unsigned long long p, float& lo, float& hi)
{
    asm("mov.b64 {%0, %1}, %2;" : "=f"(lo), "=f"(hi) : "l"(p));
}

// ---------------- fast activations ----------------
__device__ __forceinline__ float fsig(float x)
{
    float e; asm("ex2.approx.f32 %0, %1;" : "=f"(e) : "f"(-1.4426950408889634f * x));
    float r; asm("rcp.approx.f32 %0, %1;" : "=f"(r) : "f"(1.f + e));
    return r;
}
__device__ __forceinline__ float ftanh(float x)
{
    float e; asm("ex2.approx.f32 %0, %1;" : "=f"(e) : "f"(2.8853900817779268f * x));
    float r; asm("rcp.approx.f32 %0, %1;" : "=f"(r) : "f"(1.f + e));
    return 1.f - 2.f * r;
}

// ---------------- prep ----------------
__global__ void prep_k(const int* __restrict__ src, const int* __restrict__ trg,
                       float* __restrict__ out)
{
    long idx = (long)blockIdx.x * blockDim.x + threadIdx.x;
    const long N0 = (long)B_ * V_;
    if (idx < N0) {
        long b = idx / V_, v = idx - b * V_;
        out[(size_t)b * T_ * V_ + v] = 0.f;
        return;
    }
    idx -= N0;
    if (idx < 2 * H_ * B_) { g_enc_hT[idx >> 14][0][idx & 16383] = 0.f; return; }
    idx -= 2 * H_ * B_;
    if (idx < S_ * B_) {
        int t = (int)(idx / B_), b = (int)(idx % B_);
        g_enc_rowidx[idx] = src[b * S_ + t];
        return;
    }
    idx -= S_ * B_;
    if (idx < TD * B_) {
        int t = (int)(idx / B_), b = (int)(idx % B_);
        g_dec_rowidx[idx] = trg[b * T_ + t];
        return;
    }
    idx -= TD * B_;
    if (idx < 192) { g_sync[idx] = 0; return; }
    idx -= 192;
    if (idx < (MPAD - MROWS) * 2048) {
        g_Abig[(size_t)(MROWS + (idx >> 11)) * 2048 + (idx & 2047)] = __float2bfloat16(0.f);
        return;
    }
}

// ---------------- split helper ----------------
__device__ __forceinline__ void split4(float4 v, __nv_bfloat16* hi, __nv_bfloat16* lo)
{
    hi[0] = __float2bfloat16(v.x); lo[0] = __float2bfloat16(v.x - __bfloat162float(hi[0]));
    hi[1] = __float2bfloat16(v.y); lo[1] = __float2bfloat16(v.y - __bfloat162float(hi[1]));
    hi[2] = __float2bfloat16(v.z); lo[2] = __float2bfloat16(v.z - __bfloat162float(hi[2]));
    hi[3] = __float2bfloat16(v.w); lo[3] = __float2bfloat16(v.w - __bfloat162float(hi[3]));
}

// ---------------- fcW split conversion (R9-proven geometry: 1024 floats/row) ----------
__global__ void wconv_k(const float* __restrict__ fcW)
{
    size_t i = (size_t)blockIdx.x * 256 + threadIdx.x;   // over V_*256 float4s
    if (i >= (size_t)V_ * 256) return;
    size_t n = i >> 8; int k4 = (int)(i & 255);
    float4 v = __ldcg((const float4*)fcW + i);
    __nv_bfloat16 hi[4], lo[4];
    split4(v, hi, lo);
    *(uint64_t*)(g_Wbig + n * 2048 + k4 * 4)        = *(uint64_t*)hi;
    *(uint64_t*)(g_Wbig + n * 2048 + 1024 + k4 * 4) = *(uint64_t*)lo;
}

// ---------------- Wih split conversion (all 3 matrices into g_Wp) ----------------
__global__ void pwconv_k(const float* __restrict__ Wf, const float* __restrict__ Wb,
                         const float* __restrict__ Wd)
{
    size_t i = (size_t)blockIdx.x * 256 + threadIdx.x;   // over 8192*64 float4s
    if (i >= (size_t)8192 * 64) return;
    size_t row = i >> 6; int k4 = (int)(i & 63);
    const float* src;
    size_t r = row;
    if (row < 2048)      src = Wf;
    else if (row < 4096) { src = Wb; r = row - 2048; }
    else                 { src = Wd; r = row - 4096; }
    float4 v = __ldcg((const float4*)(src + r * E_) + k4);
    __nv_bfloat16 hi[4], lo[4];
    split4(v, hi, lo);
    *(uint64_t*)(g_Wp + row * 512 + k4 * 4)       = *(uint64_t*)hi;
    *(uint64_t*)(g_Wp + row * 512 + 256 + k4 * 4) = *(uint64_t*)lo;
}

// ---------------- gathered-embedding split conversion ----------------
__global__ void paconv_k(const float* __restrict__ enc_emb, const float* __restrict__ dec_emb)
{
    size_t i = (size_t)blockIdx.x * 256 + threadIdx.x;   // over 6144*64 float4s
    if (i >= (size_t)6144 * 64) return;
    size_t row = i >> 6; int k4 = (int)(i & 63);
    __nv_bfloat16* dst;
    float4 v;
    if (row < 4096) {
        v = __ldcg((const float4*)(enc_emb + (size_t)g_enc_rowidx[row] * E_) + k4);
        dst = g_Aenc + row * 512;
    } else {
        size_t m = row - 4096;
        dst = g_Adec + m * 512;
        if (m < MROWS)
            v = __ldcg((const float4*)(dec_emb + (size_t)g_dec_rowidx[m] * E_) + k4);
        else
            v = make_float4(0.f, 0.f, 0.f, 0.f);
    }
    __nv_bfloat16 hi[4], lo[4];
    split4(v, hi, lo);
    *(uint64_t*)(dst + k4 * 4)       = *(uint64_t*)hi;
    *(uint64_t*)(dst + 256 + k4 * 4) = *(uint64_t*)lo;
}

// ================= shared tcgen05 GEMM plumbing =================
#define STAGE  98304
#define OFF_AHI0 0
#define OFF_AHI1 16384
#define OFF_ALO0 32768
#define OFF_ALO1 49152
#define OFF_WHI  65536
#define OFF_WLO  81920
#define SMEM_HDR 1024
#define SMEM_TC  (SMEM_HDR + 2 * STAGE)
#define IDESC_F16 ((1u<<4)|(1u<<7)|(1u<<10)|((128u/8)<<17)|((128u/16)<<24))

static __device__ __forceinline__ uint32_t swz(uint32_t x) { return x ^ ((x >> 3) & 0x70); }

__device__ __forceinline__ uint32_t smem_u32(const void* p)
{
    uint32_t a;
    asm("{ .reg .u64 t; cvta.to.shared.u64 t, %1; cvt.u32.u64 %0, t; }" : "=r"(a) : "l"(p));
    return a;
}
__device__ __forceinline__ void cp16(uint32_t dst, const void* src)
{
    asm volatile("cp.async.cg.shared.global [%0], [%1], 16;" :: "r"(dst), "l"(src));
}

#if HAS_TC
__device__ __forceinline__ uint32_t elect1()
{
    uint32_t p;
    asm volatile("{ .reg .pred p; elect.sync _|p, 0xFFFFFFFF; selp.b32 %0, 1, 0, p; }" : "=r"(p));
    return p;
}
__device__ __forceinline__ void mma_f16_ss(uint32_t d, uint64_t ad, uint64_t bd,
                                           uint32_t idesc, uint32_t en)
{
    asm volatile(
        "{\n\t.reg .pred p;\n\tsetp.ne.u32 p, %5, 0;\n\t"
        "tcgen05.mma.cta_group::1.kind::f16 [%0], %1, %2, %3, {%4,%4,%4,%4}, p;\n\t}"
        :: "r"(d), "l"(ad), "l"(bd), "r"(idesc), "r"(0u), "r"(en) : "memory");
}

// generic chunk loader — COALESCED: each warp-instr covers 4 consecutive rows,
// lanes 0..7 sweep one row's 8x16B (full 128B line per 8 lanes).
template <int RS, int LOFF>
__device__ __forceinline__ void load_chunk_g(const __nv_bfloat16* Ag, const __nv_bfloat16* Wg,
                                             int kc, uint32_t sbase, int tid)
{
    // A: 256 rows x 128B (hi) + (lo) -> 2048 cp16 each half
#pragma unroll
    for (int g = 0; g < 8; g++) {
        int idx = g * 256 + tid;              // 0..2047
        int row = idx >> 3, c = idx & 7;
        uint32_t hb = (row < 128) ? OFF_AHI0 : OFF_AHI1;
        uint32_t lb = (row < 128) ? OFF_ALO0 : OFF_ALO1;
        uint32_t so = swz((uint32_t)(row & 127) * 128 + c * 16);
        const __nv_bfloat16* srow = Ag + (size_t)row * RS + kc + c * 8;
        cp16(sbase + hb + so, srow);
        cp16(sbase + lb + so, srow + LOFF);
    }
    // W: 128 rows x 128B (hi) + (lo) -> 1024 cp16 each half
#pragma unroll
    for (int g = 0; g < 4; g++) {
        int idx = g * 256 + tid;              // 0..1023
        int row = idx >> 3, c = idx & 7;
        uint32_t so = swz((uint32_t)row * 128 + c * 16);
        const __nv_bfloat16* srow = Wg + (size_t)row * RS + kc + c * 8;
        cp16(sbase + OFF_WHI + so, srow);
        cp16(sbase + OFF_WLO + so, srow + LOFF);
    }
    asm volatile("cp.async.commit_group;" ::: "memory");
}

// MMA + pipeline body shared by both GEMMs
template <int RS, int LOFF, int KCHN>
__device__ __forceinline__ uint32_t tc_mainloop(const __nv_bfloat16* Ag,
                                                const __nv_bfloat16* Wg,
                                                uint32_t sbase, int tid, int wid)
{
    if (wid == 0)
        asm volatile("tcgen05.alloc.cta_group::1.sync.aligned.shared::cta.b32 [%0], 512;"
                     :: "r"(sbase) : "memory");
    if (tid == 0) {
        asm volatile("mbarrier.init.shared.b64 [%0], 1;" :: "r"(sbase + 16) : "memory");
        asm volatile("mbarrier.init.shared.b64 [%0], 1;" :: "r"(sbase + 24) : "memory");
    }
    __syncthreads();
    uint32_t tmem;
    asm volatile("ld.shared.b32 %0, [%1];" : "=r"(tmem) : "r"(sbase));

    load_chunk_g<RS, LOFF>(Ag, Wg, 0, sbase + SMEM_HDR, tid);
    if (KCHN > 1) load_chunk_g<RS, LOFF>(Ag, Wg, 64, sbase + SMEM_HDR + STAGE, tid);

    int phase0 = 0, phase1 = 0;
    for (int c = 0; c < KCHN; c++) {
        const int p = c & 1;
        if (c + 1 < KCHN) asm volatile("cp.async.wait_group 1;" ::: "memory");
        else              asm volatile("cp.async.wait_group 0;" ::: "memory");
        __syncthreads();
        asm volatile("fence.proxy.async.shared::cta;" ::: "memory");

        if (wid == 0 && elect1()) {
            const uint32_t st = sbase + SMEM_HDR + p * STAGE;
            const uint64_t BASE = (uint64_t(2) << 61) | (uint64_t(1) << 46) |
                                  (uint64_t(64) << 32) | (uint64_t(1) << 16);
            uint64_t dAhi0 = BASE | (((st + OFF_AHI0) >> 4) & 0x3FFF);
            uint64_t dAhi1 = BASE | (((st + OFF_AHI1) >> 4) & 0x3FFF);
            uint64_t dAlo0 = BASE | (((st + OFF_ALO0) >> 4) & 0x3FFF);
            uint64_t dAlo1 = BASE | (((st + OFF_ALO1) >> 4) & 0x3FFF);
            uint64_t dWhi  = BASE | (((st + OFF_WHI) >> 4) & 0x3FFF);
            uint64_t dWlo  = BASE | (((st + OFF_WLO) >> 4) & 0x3FFF);
#pragma unroll
            for (int ks = 0; ks < 4; ks++) {
                uint32_t en0 = (c == 0 && ks == 0) ? 0u : 1u;
                mma_f16_ss(tmem + 0,   dAhi0 + ks * 2, dWhi + ks * 2, IDESC_F16, en0);
                mma_f16_ss(tmem + 128, dAhi1 + ks * 2, dWhi + ks * 2, IDESC_F16, en0);
                mma_f16_ss(tmem + 0,   dAhi0 + ks * 2, dWlo + ks * 2, IDESC_F16, 1u);
                mma_f16_ss(tmem + 128, dAhi1 + ks * 2, dWlo + ks * 2, IDESC_F16, 1u);
                mma_f16_ss(tmem + 0,   dAlo0 + ks * 2, dWhi + ks * 2, IDESC_F16, 1u);
                mma_f16_ss(tmem + 128, dAlo1 + ks * 2, dWhi + ks * 2, IDESC_F16, 1u);
            }
            asm volatile(
                "tcgen05.commit.cta_group::1.mbarrier::arrive::one.shared::cluster.b64 [%0];"
                :: "r"(sbase + 16 + p * 8) : "memory");
        }
        {
            uint32_t mb = sbase + 16 + p * 8;
            uint32_t ph = p ? phase1 : phase0;
            uint32_t done;
            do {
                asm volatile(
                    "{\n\t.reg .pred q;\n\t"
                    "mbarrier.try_wait.parity.shared.b64 q, [%1], %2, 0x989680;\n\t"
                    "selp.b32 %0, 1, 0, q;\n\t}"
                    : "=r"(done) : "r"(mb), "r"(ph) : "memory");
            } while (!done);
            if (p) phase1 ^= 1; else phase0 ^= 1;
        }
        if (c + 2 < KCHN)
            load_chunk_g<RS, LOFF>(Ag, Wg, (c + 2) * 64, sbase + SMEM_HDR + p * STAGE, tid);
    }
    asm volatile("tcgen05.fence::after_thread_sync;" ::: "memory");
    return tmem;
}

#define LDTM32(r, addr) \
    asm volatile( \
        "tcgen05.ld.sync.aligned.32x32b.x32.b32 " \
        "{%0,%1,%2,%3,%4,%5,%6,%7,%8,%9,%10,%11,%12,%13,%14,%15," \
        "%16,%17,%18,%19,%20,%21,%22,%23,%24,%25,%26,%27,%28,%29,%30,%31}, [%32];" \
        : "=r"((r)[0]), "=r"((r)[1]), "=r"((r)[2]), "=r"((r)[3]), "=r"((r)[4]), "=r"((r)[5]), \
          "=r"((r)[6]), "=r"((r)[7]), "=r"((r)[8]), "=r"((r)[9]), "=r"((r)[10]), "=r"((r)[11]), \
          "=r"((r)[12]), "=r"((r)[13]), "=r"((r)[14]), "=r"((r)[15]), "=r"((r)[16]), "=r"((r)[17]), \
          "=r"((r)[18]), "=r"((r)[19]), "=r"((r)[20]), "=r"((r)[21]), "=r"((r)[22]), "=r"((r)[23]), \
          "=r"((r)[24]), "=r"((r)[25]), "=r"((r)[26]), "=r"((r)[27]), "=r"((r)[28]), "=r"((r)[29]), \
          "=r"((r)[30]), "=r"((r)[31]) \
        : "r"(addr))
#endif  // HAS_TC

// ---------------- final logits GEMM ----------------
__global__ __launch_bounds__(256, 1)
void bgemm_tc(const float* __restrict__ bias, float* __restrict__ out)
{
#if HAS_TC
    extern __shared__ __align__(1024) unsigned char sm[];
    const uint32_t sbase = smem_u32(sm);
    const int tid = threadIdx.x, wid = tid >> 5, lane = tid & 31;
    const int n0 = blockIdx.x * 128;
    const int m0g = blockIdx.y * 256;
    const __nv_bfloat16* Ag = g_Abig + (size_t)m0g * 2048;
    const __nv_bfloat16* Wg = g_Wbig + (size_t)n0 * 2048;

    uint32_t tmem = tc_mainloop<2048, 1024, 16>(Ag, Wg, sbase, tid, wid);

    {
        const int sub = tid >> 7;
        const int wiw = (tid >> 5) & 3;
        const int mrow = m0g + sub * 128 + wiw * 32 + lane;
        const uint32_t warp_off = ((uint32_t)(tid & 127) >> 5) << 21;
        const uint32_t dbase = tmem + sub * 128 + warp_off;
        const bool valid = mrow < MROWS;
        const int t = mrow >> 5, b = mrow & 31;
        float* orow = out + (size_t)(b * T_ + t + 1) * V_ + n0;
#pragma unroll
        for (int q = 0; q < 4; q++) {
            uint32_t r[32];
            LDTM32(r, dbase + q * 32);
            asm volatile("tcgen05.wait::ld.sync.aligned;" ::: "memory");
            if (valid) {
#pragma unroll
                for (int c4 = 0; c4 < 8; c4++) {
                    const int n = q * 32 + c4 * 4;
                    float4 bb = *(const float4*)(bias + n0 + n);
                    float4 v;
                    v.x = __uint_as_float(r[c4 * 4 + 0]) + bb.x;
                    v.y = __uint_as_float(r[c4 * 4 + 1]) + bb.y;
                    v.z = __uint_as_float(r[c4 * 4 + 2]) + bb.z;
                    v.w = __uint_as_float(r[c4 * 4 + 3]) + bb.w;
                    *(float4*)(orow + n) = v;
                }
            }
        }
    }
    __syncthreads();
    if (wid == 0) {
        asm volatile("tcgen05.relinquish_alloc_permit.cta_group::1.sync.aligned;" ::: "memory");
        asm volatile("tcgen05.dealloc.cta_group::1.sync.aligned.b32 %0, 512;" :: "r"(tmem));
    }
#endif
}

// ---------------- pregate GEMM (tensor): C[(t*Ntot+n)*32+b] = A@W^T + bias ----------------
__global__ __launch_bounds__(256, 1)
void pgemm_tc(const __nv_bfloat16* __restrict__ A, const __nv_bfloat16* __restrict__ W,
              const float* __restrict__ bias, float* __restrict__ C,
              int Ntot, int Mvalid)
{
#if HAS_TC
    extern __shared__ __align__(1024) unsigned char sm[];
    const uint32_t sbase = smem_u32(sm);
    const int tid = threadIdx.x, wid = tid >> 5, lane = tid & 31;
    const int n0 = blockIdx.x * 128;
    const int m0g = blockIdx.y * 256;
    const __nv_bfloat16* Ag = A + (size_t)m0g * 512;
    const __nv_bfloat16* Wg = W + (size_t)n0 * 512;

    uint32_t tmem = tc_mainloop<512, 256, 4>(Ag, Wg, sbase, tid, wid);

    {
        const int sub = tid >> 7;
        const int wiw = (tid >> 5) & 3;
        const int mrow = m0g + sub * 128 + wiw * 32 + lane;
        const uint32_t warp_off = ((uint32_t)(tid & 127) >> 5) << 21;
        const uint32_t dbase = tmem + sub * 128 + warp_off;
        const bool valid = mrow < Mvalid;
        const int t = mrow >> 5, b = mrow & 31;
#pragma unroll
        for (int q = 0; q < 4; q++) {
            uint32_t r[32];
            LDTM32(r, dbase + q * 32);
            asm volatile("tcgen05.wait::ld.sync.aligned;" ::: "memory");
            if (valid) {
#pragma unroll
                for (int c1 = 0; c1 < 32; c1++) {
                    const int n = n0 + q * 32 + c1;
                    C[((size_t)t * Ntot + n) * B_ + b] = __uint_as_float(r[c1]) + bias[n];
                }
            }
        }
    }
    __syncthreads();
    if (wid == 0) {
        asm volatile("tcgen05.relinquish_alloc_permit.cta_group::1.sync.aligned;" ::: "memory");
        asm volatile("tcgen05.dealloc.cta_group::1.sync.aligned.b32 %0, 512;" :: "r"(tmem));
    }
#endif
}

// ---------------- persistent encoder (R10-proven) ----------------
__global__ void enc_persist_k(const float* __restrict__ Whh_f,
                              const float* __restrict__ Whh_b)
{
    extern __shared__ float smemf[];
    float2* sw_if = (float2*)smemf;
    float2* sw_go = (float2*)(smemf + 8192);
    float*  shT   = smemf + 16384;
    const int dir = blockIdx.x >> 6, cb = blockIdx.x & 63;
    const int w = threadIdx.x >> 5, lane = threadIdx.x & 31;
    const int j = cb * 8 + w;
    const float* Whh = dir ? Whh_b : Whh_f;
    const float* preBase = dir ? g_pre_bT : g_pre_fT;
    unsigned* cnt = &g_sync[dir * 64];
    unsigned* gen = &g_sync[dir * 64 + 32];

    {
        const int base_j = cb * 8;
        for (int idx = threadIdx.x; idx < 8 * H_; idx += 256) {
            int c = idx >> 9, k = idx & 511;
            float wi = Whh[(size_t)(0 * H_ + base_j + c) * H_ + k];
            float wf = Whh[(size_t)(1 * H_ + base_j + c) * H_ + k];
            float wg = Whh[(size_t)(2 * H_ + base_j + c) * H_ + k];
            float wo = Whh[(size_t)(3 * H_ + base_j + c) * H_ + k];
            sw_if[idx] = make_float2(wi, wf);
            sw_go[idx] = make_float2(wg, wo);
        }
    }
    __syncthreads();

    const ulonglong2* pif = (const ulonglong2*)(sw_if + (size_t)w * H_);
    const ulonglong2* pgo = (const ulonglong2*)(sw_go + (size_t)w * H_);
    float cst = 0.f;

    for (int s = 0; s < S_; s++) {
        const float4* s4 = (const float4*)g_enc_hT[dir][s & 1];
        float4* d4 = (float4*)shT;
        for (int i = threadIdx.x; i < H_ * B_ / 4; i += 256) d4[i] = __ldcg(s4 + i);
        __syncthreads();
        const int t = dir ? (S_ - 1 - s) : s;
        const float* preT = preBase + (size_t)t * GH * B_;
        unsigned long long acc_if = pk2(__ldcg(preT + (size_t)(0 * H_ + j) * B_ + lane),
                                        __ldcg(preT + (size_t)(1 * H_ + j) * B_ + lane));
        unsigned long long acc_go = pk2(__ldcg(preT + (size_t)(2 * H_ + j) * B_ + lane),
                                        __ldcg(preT + (size_t)(3 * H_ + j) * B_ + lane));
#pragma unroll 4
        for (int k4 = 0; k4 < H_ / 4; k4++) {
            ulonglong2 a01 = pif[k4 * 2], a23 = pif[k4 * 2 + 1];
            ulonglong2 g01 = pgo[k4 * 2], g23 = pgo[k4 * 2 + 1];
            float h0 = shT[(k4 * 4 + 0) * B_ + lane];
            float h1 = shT[(k4 * 4 + 1) * B_ + lane];
            float h2 = shT[(k4 * 4 + 2) * B_ + lane];
            float h3 = shT[(k4 * 4 + 3) * B_ + lane];
            unsigned long long H0 = pk2(h0, h0), H1 = pk2(h1, h1);
            unsigned long long H2 = pk2(h2, h2), H3 = pk2(h3, h3);
            acc_if = ffma2(a01.x, H0, acc_if);
            acc_if = ffma2(a01.y, H1, acc_if);
            acc_if = ffma2(a23.x, H2, acc_if);
            acc_if = ffma2(a23.y, H3, acc_if);
            acc_go = ffma2(g01.x, H0, acc_go);
            acc_go = ffma2(g01.y, H1, acc_go);
            acc_go = ffma2(g23.x, H2, acc_go);
            acc_go = ffma2(g23.y, H3, acc_go);
        }
        float ai, af, ag, ao;
        unpk2(acc_if, ai, af);
        unpk2(acc_go, ag, ao);
        float iv = fsig(ai), fv = fsig(af), gv = ftanh(ag), ov = fsig(ao);
        cst = fv * cst + iv * gv;
        __stcg(&g_enc_hT[dir][(s + 1) & 1][(size_t)j * B_ + lane], ov * ftanh(cst));
        if (s == S_ - 1) g_enc_cT[dir][(size_t)j * B_ + lane] = cst;
        grid_barrier2(cnt, gen, (unsigned)(s + 1), 64u);
    }
}

// ---------------- persistent decoder (R10-proven) ----------------
__global__ void dec_persist_k(const float* __restrict__ Whh)
{
    extern __shared__ float smemf[];
    float2* sw_if = (float2*)smemf;
    float2* sw_go = (float2*)(smemf + 16384);
    float*  shH   = smemf + 32768;
    const int w = threadIdx.x >> 5, lane = threadIdx.x & 31;
    const int j = blockIdx.x * 8 + w;
    unsigned* cnt = &g_sync[128];
    unsigned* gen = &g_sync[160];

    {
        const int base_j = blockIdx.x * 8;
        for (int idx = threadIdx.x; idx < 8 * DH; idx += 256) {
            int c = idx >> 10, k = idx & 1023;
            float wi = Whh[(size_t)(0 * DH + base_j + c) * DH + k];
            float wf = Whh[(size_t)(1 * DH + base_j + c) * DH + k];
            float wg = Whh[(size_t)(2 * DH + base_j + c) * DH + k];
            float wo = Whh[(size_t)(3 * DH + base_j + c) * DH + k];
            sw_if[idx] = make_float2(wi, wf);
            sw_go[idx] = make_float2(wg, wo);
        }
    }

    float cst, h0v;
    if (j < H_) { cst = g_enc_cT[0][j * B_ + lane]; h0v = g_enc_hT[0][0][j * B_ + lane]; }
    else { cst = g_enc_cT[1][(j - H_) * B_ + lane]; h0v = g_enc_hT[1][0][(j - H_) * B_ + lane]; }
    __stcg(&g_dec_hT[0][(size_t)j * B_ + lane], h0v);
    grid_barrier2(cnt, gen, 1u, 128u);

    for (int t = 0; t < TD; t++) {
        const float* preT = g_dec_preT + (size_t)t * DG * B_;
        unsigned long long acc_if = pk2(__ldcg(preT + (size_t)(0 * DH + j) * B_ + lane),
                                        __ldcg(preT + (size_t)(1 * DH + j) * B_ + lane));
        unsigned long long acc_go = pk2(__ldcg(preT + (size_t)(2 * DH + j) * B_ + lane),
                                        __ldcg(preT + (size_t)(3 * DH + j) * B_ + lane));

#pragma unroll
        for (int half = 0; half < 2; half++) {
            const float4* s4 = (const float4*)g_dec_hT[t & 1] + half * 4096;
            float4* d4 = (float4*)shH;
            for (int i = threadIdx.x; i < 4096; i += 256) d4[i] = __ldcg(s4 + i);
            __syncthreads();
            const ulonglong2* pif =
                (const ulonglong2*)(sw_if + (size_t)w * DH) + half * 256;
            const ulonglong2* pgo =
                (const ulonglong2*)(sw_go + (size_t)w * DH) + half * 256;
#pragma unroll 4
            for (int k4 = 0; k4 < 128; k4++) {
                ulonglong2 a01 = pif[k4 * 2], a23 = pif[k4 * 2 + 1];
                ulonglong2 g01 = pgo[k4 * 2], g23 = pgo[k4 * 2 + 1];
                float h0 = shH[(k4 * 4 + 0) * B_ + lane];
                float h1 = shH[(k4 * 4 + 1) * B_ + lane];
                float h2 = shH[(k4 * 4 + 2) * B_ + lane];
                float h3 = shH[(k4 * 4 + 3) * B_ + lane];
                unsigned long long H0 = pk2(h0, h0), H1 = pk2(h1, h1);
                unsigned long long H2 = pk2(h2, h2), H3 = pk2(h3, h3);
                acc_if = ffma2(a01.x, H0, acc_if);
                acc_if = ffma2(a01.y, H1, acc_if);
                acc_if = ffma2(a23.x, H2, acc_if);
                acc_if = ffma2(a23.y, H3, acc_if);
                acc_go = ffma2(g01.x, H0, acc_go);
                acc_go = ffma2(g01.y, H1, acc_go);
                acc_go = ffma2(g23.x, H2, acc_go);
                acc_go = ffma2(g23.y, H3, acc_go);
            }
            if (half == 0) __syncthreads();
        }

        float ai, af, ag, ao;
        unpk2(acc_if, ai, af);
        unpk2(acc_go, ag, ao);
        float iv = fsig(ai), fv = fsig(af), gv = ftanh(ag), ov = fsig(ao);
        cst = fv * cst + iv * gv;
        float hv = ov * ftanh(cst);
        __stcg(&g_dec_hT[(t + 1) & 1][(size_t)j * B_ + lane], hv);
        size_t m = (size_t)t * B_ + lane;
        __nv_bfloat16 hi = __float2bfloat16(hv);
        g_Abig[m * 2048 + j] = hi;
        g_Abig[m * 2048 + 1024 + j] = __float2bfloat16(hv - __bfloat162float(hi));
        grid_barrier2(cnt, gen, (unsigned)(t + 2), 128u);
    }
}

// ---------------- launch ----------------
extern "C" void kernel_launch(void* const* d_in, const int* in_sizes, int n_in,
                              void* d_out, int out_size)
{
    (void)in_sizes; (void)n_in; (void)out_size;
    const int*   src     = (const int*)d_in[0];
    const int*   trg     = (const int*)d_in[1];
    const float* enc_emb = (const float*)d_in[2];
    const float* dec_emb = (const float*)d_in[3];
    const float* eWih_f  = (const float*)d_in[4];
    const float* eWhh_f  = (const float*)d_in[5];
    const float* eb_f    = (const float*)d_in[6];
    const float* eWih_b  = (const float*)d_in[7];
    const float* eWhh_b  = (const float*)d_in[8];
    const float* eb_b    = (const float*)d_in[9];
    const float* dWih    = (const float*)d_in[10];
    const float* dWhh    = (const float*)d_in[11];
    const float* db      = (const float*)d_in[12];
    const float* fcW     = (const float*)d_in[13];
    const float* fcb     = (const float*)d_in[14];
    float* out = (float*)d_out;

    cudaFuncSetAttribute(enc_persist_k, cudaFuncAttributeMaxDynamicSharedMemorySize, 131072);
    cudaFuncSetAttribute(dec_persist_k, cudaFuncAttributeMaxDynamicSharedMemorySize, 196608);
    cudaFuncSetAttribute(bgemm_tc, cudaFuncAttributeMaxDynamicSharedMemorySize, SMEM_TC);
    cudaFuncSetAttribute(pgemm_tc, cudaFuncAttributeMaxDynamicSharedMemorySize, SMEM_TC);

    void *p_pre_fT, *p_pre_bT, *p_dec_preT, *p_Wp, *p_Aenc, *p_Adec;
    cudaGetSymbolAddress(&p_pre_fT, g_pre_fT);
    cudaGetSymbolAddress(&p_pre_bT, g_pre_bT);
    cudaGetSymbolAddress(&p_dec_preT, g_dec_preT);
    cudaGetSymbolAddress(&p_Wp, g_Wp);
    cudaGetSymbolAddress(&p_Aenc, g_Aenc);
    cudaGetSymbolAddress(&p_Adec, g_Adec);
    __nv_bfloat16* Wp = (__nv_bfloat16*)p_Wp;

    long total = (long)B_ * V_ + 2L * H_ * B_ + (long)S_ * B_ + (long)TD * B_
               + 192 + (long)(MPAD - MROWS) * 2048;
    prep_k<<<(unsigned)((total + 255) / 256), 256>>>(src, trg, out);
    wconv_k<<<V_, 256>>>(fcW);
    pwconv_k<<<2048, 256>>>(eWih_f, eWih_b, dWih);
    paconv_k<<<1536, 256>>>(enc_emb, dec_emb);

    pgemm_tc<<<dim3(16, 16), 256, SMEM_TC>>>(
        (const __nv_bfloat16*)p_Aenc, Wp, eb_f, (float*)p_pre_fT, GH, 4096);
    pgemm_tc<<<dim3(16, 16), 256, SMEM_TC>>>(
        (const __nv_bfloat16*)p_Aenc, Wp + (size_t)2048 * 512, eb_b, (float*)p_pre_bT, GH, 4096);
    pgemm_tc<<<dim3(32, 8), 256, SMEM_TC>>>(
        (const __nv_bfloat16*)p_Adec, Wp + (size_t)4096 * 512, db, (float*)p_dec_preT, DG, MROWS);

    enc_persist_k<<<128, 256, 131072>>>(eWhh_f, eWhh_b);
    dec_persist_k<<<128, 256, 196608>>>(dWhh);

    bgemm_tc<<<dim3(V_ / 128, MPAD / 256), 256, SMEM_TC>>>(fcb, out);
}